// round 1
// baseline (speedup 1.0000x reference)
#include <cuda_runtime.h>

#define EPSN 1e-5f

// ---------------- scratch (device globals; no allocations allowed) ----------
__device__ float g_h1[32*16*128*128];     // conv1 raw output
__device__ float g_enc[32*64*64*64];      // conv2 raw output
__device__ float g_dec_in[32*64*64*64];   // quantized (flat - residual), NCHW
__device__ float g_d1[32*16*128*128];     // deconv1 raw output
__device__ float g_m1[512],  g_v1[512];   // instance-norm stats for h1 (n*16+c)
__device__ float g_m2[2048], g_v2[2048];  // instance-norm stats for enc (n*64+c)
__device__ float g_bn_s[16], g_bn_q[16];  // batchnorm sums
__device__ float g_loss;

extern __shared__ float dynsm[];

typedef unsigned long long ull;

// packed f32x2 fma: acc = a*b + acc (elementwise on both lanes)
#define FMA2(acc, a, b_) asm("fma.rn.f32x2 %0, %1, %2, %3;" : "=l"(acc) : "l"(a), "l"(b_), "l"(acc))

__device__ __forceinline__ float2 unpack2(ull p){
    float2 f; asm("mov.b64 {%0,%1}, %2;" : "=f"(f.x), "=f"(f.y) : "l"(p)); return f;
}
__device__ __forceinline__ ull pack2(float lo, float hi){
    ull p; asm("mov.b64 %0, {%1,%2};" : "=l"(p) : "f"(lo), "f"(hi)); return p;
}

__device__ __forceinline__ float warpsum(float v){
    #pragma unroll
    for (int o = 16; o; o >>= 1) v += __shfl_down_sync(0xffffffffu, v, o);
    return v;
}

// ---------------- zero accumulators ----------------------------------------
__global__ void k_zero(){
    int t = threadIdx.x;
    if (t == 0) g_loss = 0.f;
    if (t < 16){ g_bn_s[t] = 0.f; g_bn_q[t] = 0.f; }
}

// ---------------- conv1: x[32,3,256,256] -> g_h1[32,16,128,128] -------------
__global__ __launch_bounds__(256) void k_conv1(const float* __restrict__ x,
                                               const float* __restrict__ w,
                                               const float* __restrict__ b){
    __shared__ float wsm[48][16];   // (ci*16+kh*4+kw) x co
    int tid = threadIdx.x;
    for (int i = tid; i < 768; i += 256){
        int co = i / 48, idx = i % 48;
        wsm[idx][co] = w[i];
    }
    __syncthreads();
    int n   = blockIdx.x >> 6;
    int pos = ((blockIdx.x & 63) << 8) + tid;
    int oh = pos >> 7, ow = pos & 127;
    float acc[16];
    #pragma unroll
    for (int co = 0; co < 16; co++) acc[co] = b[co];
    const float* xn = x + (size_t)n * 3 * 65536;
    for (int ci = 0; ci < 3; ci++){
        #pragma unroll
        for (int kh = 0; kh < 4; kh++){
            int ih = 2*oh + kh - 1;
            if ((unsigned)ih >= 256u) continue;
            const float* row = xn + (ci*256 + ih)*256;
            #pragma unroll
            for (int kw = 0; kw < 4; kw++){
                int iw = 2*ow + kw - 1;
                if ((unsigned)iw >= 256u) continue;
                float v = row[iw];
                const float* wr = wsm[ci*16 + kh*4 + kw];
                #pragma unroll
                for (int co = 0; co < 16; co++) acc[co] = fmaf(v, wr[co], acc[co]);
            }
        }
    }
    float* outp = g_h1 + (size_t)n * 16 * 16384 + oh*128 + ow;
    #pragma unroll
    for (int co = 0; co < 16; co++) outp[(size_t)co * 16384] = acc[co];
}

// ---------------- per-plane mean/var (instance norm stats) ------------------
// mode 0: g_h1, 512 planes of 16384 -> g_m1/g_v1
// mode 1: g_enc, 2048 planes of 4096 -> g_m2/g_v2
__global__ __launch_bounds__(256) void k_stats(int mode){
    int p = blockIdx.x;
    const float* sp; float* mo; float* vo; int plane;
    if (mode == 0){ sp = g_h1 + (size_t)p*16384; mo = g_m1; vo = g_v1; plane = 16384; }
    else          { sp = g_enc + (size_t)p*4096; mo = g_m2; vo = g_v2; plane = 4096; }
    float s = 0.f, q = 0.f;
    for (int i = threadIdx.x; i < plane; i += 256){
        float xv = sp[i]; s += xv; q = fmaf(xv, xv, q);
    }
    __shared__ float rsum[8], rsq[8];
    s = warpsum(s); q = warpsum(q);
    int wid = threadIdx.x >> 5, lane = threadIdx.x & 31;
    if (lane == 0){ rsum[wid] = s; rsq[wid] = q; }
    __syncthreads();
    if (threadIdx.x == 0){
        float S = 0.f, Q = 0.f;
        #pragma unroll
        for (int i = 0; i < 8; i++){ S += rsum[i]; Q += rsq[i]; }
        float inv = 1.f / (float)plane;
        float mm = S * inv;
        mo[p] = mm;
        vo[p] = Q * inv - mm*mm;
    }
}

// ---------------- conv2: relu(IN(g_h1)) -> g_enc[32,64,64,64] ---------------
__global__ __launch_bounds__(256) void k_conv2(const float* __restrict__ w,
                                               const float* __restrict__ b){
    float* wsm = dynsm;            // 16384 : (ci*16+kh*4+kw)*64 + co
    float* msm = dynsm + 16384;    // 16
    float* rsm = msm + 16;         // 16
    int tid = threadIdx.x;
    for (int i = tid; i < 16384; i += 256){
        int co = i >> 8, idx = i & 255;
        wsm[idx*64 + co] = w[i];
    }
    int n = blockIdx.x >> 4;
    if (tid < 16){
        msm[tid] = g_m1[n*16 + tid];
        rsm[tid] = rsqrtf(g_v1[n*16 + tid] + EPSN);
    }
    __syncthreads();
    int pos = ((blockIdx.x & 15) << 8) + tid;
    int oh = pos >> 6, ow = pos & 63;
    float acc[64];
    #pragma unroll
    for (int co = 0; co < 64; co++) acc[co] = b[co];
    const float* hn = g_h1 + (size_t)n * 16 * 16384;
    for (int ci = 0; ci < 16; ci++){
        float mm = msm[ci], rr = rsm[ci];
        #pragma unroll
        for (int kh = 0; kh < 4; kh++){
            int ih = 2*oh + kh - 1;
            if ((unsigned)ih >= 128u) continue;
            const float* row = hn + (ci*128 + ih)*128;
            #pragma unroll
            for (int kw = 0; kw < 4; kw++){
                int iw = 2*ow + kw - 1;
                if ((unsigned)iw >= 128u) continue;
                float v = fmaxf((row[iw] - mm) * rr, 0.f);
                const float4* wr = (const float4*)(wsm + (ci*16 + kh*4 + kw)*64);
                #pragma unroll
                for (int c4 = 0; c4 < 16; c4++){
                    float4 ww = wr[c4];
                    acc[c4*4+0] = fmaf(v, ww.x, acc[c4*4+0]);
                    acc[c4*4+1] = fmaf(v, ww.y, acc[c4*4+1]);
                    acc[c4*4+2] = fmaf(v, ww.z, acc[c4*4+2]);
                    acc[c4*4+3] = fmaf(v, ww.w, acc[c4*4+3]);
                }
            }
        }
    }
    float* outp = g_enc + (size_t)n * 64 * 4096 + oh*64 + ow;
    #pragma unroll
    for (int co = 0; co < 64; co++) outp[(size_t)co * 4096] = acc[co];
}

// ---------------- RVQ: 6 stages, argmin + residual update + loss ------------
// grid 256 blocks x 512 threads; 1 vector (64 dims) per thread in registers.
__global__ __launch_bounds__(512) void k_rvq(const float* __restrict__ cb_all){
    float* cbsm  = dynsm;             // 32768 (512x64)
    float* norms = dynsm + 32768;     // 512
    float* msm   = norms + 512;       // 64
    float* rsm   = msm + 64;          // 64
    float* red   = rsm + 64;          // 16
    int tid = threadIdx.x;
    int vec = blockIdx.x * 512 + tid;
    int n   = vec >> 12;
    int pix = vec & 4095;
    if (tid < 64){
        msm[tid] = g_m2[n*64 + tid];
        rsm[tid] = rsqrtf(g_v2[n*64 + tid] + EPSN);
    }
    __syncthreads();
    const float* encp = g_enc + (size_t)n * 64 * 4096 + pix;
    ull r2[32];
    #pragma unroll
    for (int d = 0; d < 32; d++){
        float lo = fmaxf((encp[(size_t)(2*d  )*4096] - msm[2*d  ]) * rsm[2*d  ], 0.f);
        float hi = fmaxf((encp[(size_t)(2*d+1)*4096] - msm[2*d+1]) * rsm[2*d+1], 0.f);
        r2[d] = pack2(lo, hi);
    }
    float lossacc = 0.f;
    const ull NEG1 = pack2(-1.f, -1.f);

    for (int st = 0; st < 6; st++){
        __syncthreads();   // previous stage's smem reads done
        // load stage codebook (512x64 f32) cooperatively
        {
            const float4* src = (const float4*)(cb_all + (size_t)st * 32768);
            float4* dst = (float4*)cbsm;
            for (int i = tid; i < 8192; i += 512) dst[i] = src[i];
        }
        __syncthreads();
        // code norms
        if (tid < 512){
            int k = tid;
            const float4* rowp = (const float4*)(cbsm + k*64);
            float s = 0.f;
            #pragma unroll
            for (int i = 0; i < 16; i++){
                float4 e = rowp[i];
                s = fmaf(e.x,e.x, fmaf(e.y,e.y, fmaf(e.z,e.z, fmaf(e.w,e.w, s))));
            }
            norms[k] = s;
        }
        __syncthreads();
        // argmin over 512 codes, 4 at a time, packed f32x2 dot products
        float best = 3.4e38f; int bestk = 0;
        for (int k = 0; k < 512; k += 4){
            ull a0 = 0, a1 = 0, a2 = 0, a3 = 0;
            const ulonglong2* q0 = (const ulonglong2*)(cbsm + (k+0)*64);
            const ulonglong2* q1 = (const ulonglong2*)(cbsm + (k+1)*64);
            const ulonglong2* q2 = (const ulonglong2*)(cbsm + (k+2)*64);
            const ulonglong2* q3 = (const ulonglong2*)(cbsm + (k+3)*64);
            #pragma unroll
            for (int i = 0; i < 16; i++){
                ulonglong2 e0 = q0[i], e1 = q1[i], e2 = q2[i], e3 = q3[i];
                FMA2(a0, r2[2*i], e0.x); FMA2(a0, r2[2*i+1], e0.y);
                FMA2(a1, r2[2*i], e1.x); FMA2(a1, r2[2*i+1], e1.y);
                FMA2(a2, r2[2*i], e2.x); FMA2(a2, r2[2*i+1], e2.y);
                FMA2(a3, r2[2*i], e3.x); FMA2(a3, r2[2*i+1], e3.y);
            }
            float2 f0 = unpack2(a0), f1 = unpack2(a1), f2 = unpack2(a2), f3 = unpack2(a3);
            float s0 = fmaf(-2.f, f0.x + f0.y, norms[k+0]);
            float s1 = fmaf(-2.f, f1.x + f1.y, norms[k+1]);
            float s2 = fmaf(-2.f, f2.x + f2.y, norms[k+2]);
            float s3 = fmaf(-2.f, f3.x + f3.y, norms[k+3]);
            if (s0 < best){ best = s0; bestk = k; }
            if (s1 < best){ best = s1; bestk = k+1; }
            if (s2 < best){ best = s2; bestk = k+2; }
            if (s3 < best){ best = s3; bestk = k+3; }
        }
        // subtract chosen code, accumulate loss = sum(r_new^2)
        const ulonglong2* qb = (const ulonglong2*)(cbsm + bestk*64);
        ull sq = 0;
        #pragma unroll
        for (int i = 0; i < 16; i++){
            ulonglong2 e = qb[i];
            FMA2(r2[2*i],   e.x, NEG1);
            FMA2(r2[2*i+1], e.y, NEG1);
            FMA2(sq, r2[2*i],   r2[2*i]);
            FMA2(sq, r2[2*i+1], r2[2*i+1]);
        }
        float2 fq = unpack2(sq);
        lossacc += fq.x + fq.y;
    }
    // block reduce loss, one atomic per block
    lossacc = warpsum(lossacc);
    int wid = tid >> 5, lane = tid & 31;
    if (lane == 0) red[wid] = lossacc;
    __syncthreads();
    if (tid == 0){
        float S = 0.f;
        #pragma unroll
        for (int i = 0; i < 16; i++) S += red[i];
        atomicAdd(&g_loss, S * (1.25f / (131072.f * 64.f)));
    }
    // dec_in = flat - residual  (flat recomputed from enc)
    float* dp = g_dec_in + (size_t)n * 64 * 4096 + pix;
    #pragma unroll
    for (int d = 0; d < 32; d++){
        float2 rr = unpack2(r2[d]);
        float lo = fmaxf((encp[(size_t)(2*d  )*4096] - msm[2*d  ]) * rsm[2*d  ], 0.f);
        float hi = fmaxf((encp[(size_t)(2*d+1)*4096] - msm[2*d+1]) * rsm[2*d+1], 0.f);
        dp[(size_t)(2*d  )*4096] = lo - rr.x;
        dp[(size_t)(2*d+1)*4096] = hi - rr.y;
    }
}

// ---------------- deconv1: g_dec_in[32,64,64,64] -> g_d1[32,16,128,128] -----
__global__ __launch_bounds__(256) void k_deconv1(const float* __restrict__ w,
                                                 const float* __restrict__ b){
    float* wsm = dynsm;   // 16384 : (ci*16+kh*4+kw)*16 + co
    int tid = threadIdx.x;
    for (int i = tid; i < 16384; i += 256){
        int co = i >> 10, idx = i & 1023;
        wsm[idx*16 + co] = w[i];
    }
    __syncthreads();
    int n   = blockIdx.x >> 6;
    int pos = ((blockIdx.x & 63) << 8) + tid;
    int oh = pos >> 7, ow = pos & 127;
    float acc[16];
    #pragma unroll
    for (int co = 0; co < 16; co++) acc[co] = b[co];
    int p = oh & 1, q = ow & 1;
    int ih0 = (oh + p - 2) >> 1, ih1 = (oh + p) >> 1;
    int iw0 = (ow + q - 2) >> 1, iw1 = (ow + q) >> 1;
    bool vh0 = (unsigned)ih0 < 64u, vh1 = (unsigned)ih1 < 64u;
    bool vw0 = (unsigned)iw0 < 64u, vw1 = (unsigned)iw1 < 64u;
    const float* din = g_dec_in + (size_t)n * 64 * 4096;
    for (int ci = 0; ci < 64; ci++){
        const float* pl = din + ci*4096;
        float v00 = (vh0 && vw0) ? pl[ih0*64 + iw0] : 0.f;
        float v01 = (vh0 && vw1) ? pl[ih0*64 + iw1] : 0.f;
        float v10 = (vh1 && vw0) ? pl[ih1*64 + iw0] : 0.f;
        float v11 = (vh1 && vw1) ? pl[ih1*64 + iw1] : 0.f;
        const float4* w00 = (const float4*)(wsm + (ci*16 + p*4     + q    )*16);
        const float4* w01 = (const float4*)(wsm + (ci*16 + p*4     + q + 2)*16);
        const float4* w10 = (const float4*)(wsm + (ci*16 + (p+2)*4 + q    )*16);
        const float4* w11 = (const float4*)(wsm + (ci*16 + (p+2)*4 + q + 2)*16);
        #pragma unroll
        for (int c4 = 0; c4 < 4; c4++){
            float4 a = w00[c4], bb = w01[c4], c = w10[c4], d = w11[c4];
            acc[c4*4+0] = fmaf(v00,a.x, fmaf(v01,bb.x, fmaf(v10,c.x, fmaf(v11,d.x, acc[c4*4+0]))));
            acc[c4*4+1] = fmaf(v00,a.y, fmaf(v01,bb.y, fmaf(v10,c.y, fmaf(v11,d.y, acc[c4*4+1]))));
            acc[c4*4+2] = fmaf(v00,a.z, fmaf(v01,bb.z, fmaf(v10,c.z, fmaf(v11,d.z, acc[c4*4+2]))));
            acc[c4*4+3] = fmaf(v00,a.w, fmaf(v01,bb.w, fmaf(v10,c.w, fmaf(v11,d.w, acc[c4*4+3]))));
        }
    }
    float* outp = g_d1 + (size_t)n * 16 * 16384 + oh*128 + ow;
    #pragma unroll
    for (int co = 0; co < 16; co++) outp[(size_t)co * 16384] = acc[co];
}

// ---------------- batchnorm stats over g_d1 (per channel, N*H*W) ------------
__global__ __launch_bounds__(256) void k_bnstats(){
    int c = blockIdx.x & 15, nn = blockIdx.x >> 4;
    const float* sp = g_d1 + (size_t)(nn*16 + c) * 16384;
    float s = 0.f, q = 0.f;
    for (int i = threadIdx.x; i < 16384; i += 256){
        float xv = sp[i]; s += xv; q = fmaf(xv, xv, q);
    }
    __shared__ float rsum[8], rsq[8];
    s = warpsum(s); q = warpsum(q);
    int wid = threadIdx.x >> 5, lane = threadIdx.x & 31;
    if (lane == 0){ rsum[wid] = s; rsq[wid] = q; }
    __syncthreads();
    if (threadIdx.x == 0){
        float S = 0.f, Q = 0.f;
        #pragma unroll
        for (int i = 0; i < 8; i++){ S += rsum[i]; Q += rsq[i]; }
        atomicAdd(&g_bn_s[c], S);
        atomicAdd(&g_bn_q[c], Q);
    }
}

// ---------------- deconv2: BN(g_d1) -> decoded[32,3,256,256] ----------------
__global__ __launch_bounds__(256) void k_deconv2(const float* __restrict__ w,
                                                 const float* __restrict__ b,
                                                 const float* __restrict__ gamma,
                                                 const float* __restrict__ beta,
                                                 float* __restrict__ out){
    __shared__ float wsm[768];        // (ci*16+kh*4+kw)*3 + co
    __shared__ float Asm[16], Bsm[16];
    int tid = threadIdx.x;
    for (int i = tid; i < 768; i += 256){
        int co = i / 256, idx = i % 256;
        wsm[idx*3 + co] = w[i];
    }
    if (tid < 16){
        const float Nc = 32.f * 128.f * 128.f;
        float m = g_bn_s[tid] / Nc;
        float var = g_bn_q[tid] / Nc - m*m;
        float A = rsqrtf(var + EPSN) * gamma[tid];
        Asm[tid] = A;
        Bsm[tid] = fmaf(-m, A, beta[tid]);
    }
    __syncthreads();
    int n   = blockIdx.x >> 8;
    int pos = ((blockIdx.x & 255) << 8) + tid;
    int oh = pos >> 8, ow = pos & 255;
    float a0 = b[0], a1 = b[1], a2 = b[2];
    int p = oh & 1, q = ow & 1;
    int ih0 = (oh + p - 2) >> 1, ih1 = (oh + p) >> 1;
    int iw0 = (ow + q - 2) >> 1, iw1 = (ow + q) >> 1;
    bool vh0 = (unsigned)ih0 < 128u, vh1 = (unsigned)ih1 < 128u;
    bool vw0 = (unsigned)iw0 < 128u, vw1 = (unsigned)iw1 < 128u;
    const float* din = g_d1 + (size_t)n * 16 * 16384;
    for (int ci = 0; ci < 16; ci++){
        const float* pl = din + ci*16384;
        float A = Asm[ci], Bv = Bsm[ci];
        float v00 = (vh0 && vw0) ? fmaf(pl[ih0*128 + iw0], A, Bv) : 0.f;
        float v01 = (vh0 && vw1) ? fmaf(pl[ih0*128 + iw1], A, Bv) : 0.f;
        float v10 = (vh1 && vw0) ? fmaf(pl[ih1*128 + iw0], A, Bv) : 0.f;
        float v11 = (vh1 && vw1) ? fmaf(pl[ih1*128 + iw1], A, Bv) : 0.f;
        const float* w00 = wsm + (ci*16 + p*4     + q    )*3;
        const float* w01 = wsm + (ci*16 + p*4     + q + 2)*3;
        const float* w10 = wsm + (ci*16 + (p+2)*4 + q    )*3;
        const float* w11 = wsm + (ci*16 + (p+2)*4 + q + 2)*3;
        a0 = fmaf(v00,w00[0], fmaf(v01,w01[0], fmaf(v10,w10[0], fmaf(v11,w11[0], a0))));
        a1 = fmaf(v00,w00[1], fmaf(v01,w01[1], fmaf(v10,w10[1], fmaf(v11,w11[1], a1))));
        a2 = fmaf(v00,w00[2], fmaf(v01,w01[2], fmaf(v10,w10[2], fmaf(v11,w11[2], a2))));
    }
    float* outp = out + (size_t)n * 3 * 65536 + oh*256 + ow;
    outp[0]      = a0;
    outp[65536]  = a1;
    outp[131072] = a2;
}

__global__ void k_write_loss(float* __restrict__ out, int idx){
    if (threadIdx.x == 0) out[idx] = g_loss;
}

// ---------------- launch -----------------------------------------------------
extern "C" void kernel_launch(void* const* d_in, const int* in_sizes, int n_in,
                              void* d_out, int out_size){
    const float* x     = (const float*)d_in[0];
    const float* ew1   = (const float*)d_in[1];
    const float* eb1   = (const float*)d_in[2];
    const float* ew2   = (const float*)d_in[3];
    const float* eb2   = (const float*)d_in[4];
    const float* cb    = (const float*)d_in[5];
    const float* dw1   = (const float*)d_in[6];
    const float* db1   = (const float*)d_in[7];
    const float* gamma = (const float*)d_in[8];
    const float* beta  = (const float*)d_in[9];
    const float* dw2   = (const float*)d_in[10];
    const float* db2   = (const float*)d_in[11];
    float* out = (float*)d_out;

    cudaFuncSetAttribute(k_conv2,   cudaFuncAttributeMaxDynamicSharedMemorySize, 16416*4);
    cudaFuncSetAttribute(k_rvq,     cudaFuncAttributeMaxDynamicSharedMemorySize, 33424*4);
    cudaFuncSetAttribute(k_deconv1, cudaFuncAttributeMaxDynamicSharedMemorySize, 16384*4);

    k_zero<<<1, 32>>>();
    k_conv1<<<2048, 256>>>(x, ew1, eb1);
    k_stats<<<512, 256>>>(0);
    k_conv2<<<512, 256, 16416*4>>>(ew2, eb2);
    k_stats<<<2048, 256>>>(1);
    k_rvq<<<256, 512, 33424*4>>>(cb);
    k_deconv1<<<2048, 256, 16384*4>>>(dw1, db1);
    k_bnstats<<<512, 256>>>();
    k_deconv2<<<8192, 256>>>(dw2, db2, gamma, beta, out);
    k_write_loss<<<1, 32>>>(out, out_size - 1);
}

// round 2
// speedup vs baseline: 1.0065x; 1.0065x over previous
#include <cuda_runtime.h>

#define EPSN 1e-5f

// ---------------- scratch (device globals; no allocations allowed) ----------
__device__ float g_h1[32*16*128*128];     // conv1 output (normalized in-place)
__device__ float g_enc[32*64*64*64];      // conv2 output (normalized in-place)
__device__ float g_dec_in[32*64*64*64];   // quantized (flat - residual), NCHW
__device__ float g_d1[32*16*128*128];     // deconv1 raw output
__device__ float g_m1[512],  g_v1[512];   // instance-norm stats for h1 (n*16+c)
__device__ float g_m2[2048], g_v2[2048];  // instance-norm stats for enc (n*64+c)
__device__ float g_bn_s[16], g_bn_q[16];  // batchnorm sums
__device__ float g_loss;

extern __shared__ float dynsm[];

typedef unsigned long long ull;

// packed f32x2 fma: acc = a*b + acc (elementwise on both lanes)
#define FMA2(acc, a, b_) asm("fma.rn.f32x2 %0, %1, %2, %3;" : "=l"(acc) : "l"(a), "l"(b_), "l"(acc))

__device__ __forceinline__ float2 unpack2(ull p){
    float2 f; asm("mov.b64 {%0,%1}, %2;" : "=f"(f.x), "=f"(f.y) : "l"(p)); return f;
}
__device__ __forceinline__ ull pack2(float lo, float hi){
    ull p; asm("mov.b64 %0, {%1,%2};" : "=l"(p) : "f"(lo), "f"(hi)); return p;
}

__device__ __forceinline__ float warpsum(float v){
    #pragma unroll
    for (int o = 16; o; o >>= 1) v += __shfl_down_sync(0xffffffffu, v, o);
    return v;
}

// ---------------- zero accumulators ----------------------------------------
__global__ void k_zero(){
    int t = threadIdx.x;
    if (t == 0) g_loss = 0.f;
    if (t < 16){ g_bn_s[t] = 0.f; g_bn_q[t] = 0.f; }
}

// ---------------- conv1: x[32,3,256,256] -> g_h1[32,16,128,128] (f32x2) -----
__global__ __launch_bounds__(256) void k_conv1(const float* __restrict__ x,
                                               const float* __restrict__ w,
                                               const float* __restrict__ b){
    __shared__ float wsm[48][16];   // (ci*16+kh*4+kw) x co, co-pairs contiguous
    int tid = threadIdx.x;
    for (int i = tid; i < 768; i += 256){
        int co = i / 48, idx = i % 48;
        wsm[idx][co] = w[i];
    }
    __syncthreads();
    int n   = blockIdx.x >> 6;
    int pos = ((blockIdx.x & 63) << 8) + tid;
    int oh = pos >> 7, ow = pos & 127;
    ull acc[8];
    #pragma unroll
    for (int j = 0; j < 8; j++) acc[j] = pack2(b[2*j], b[2*j+1]);
    const float* xn = x + (size_t)n * 3 * 65536;
    for (int ci = 0; ci < 3; ci++){
        #pragma unroll
        for (int kh = 0; kh < 4; kh++){
            int ih = 2*oh + kh - 1;
            if ((unsigned)ih >= 256u) continue;
            const float* row = xn + (ci*256 + ih)*256;
            #pragma unroll
            for (int kw = 0; kw < 4; kw++){
                int iw = 2*ow + kw - 1;
                if ((unsigned)iw >= 256u) continue;
                float v = row[iw];
                ull v2 = pack2(v, v);
                const ull* wr = (const ull*)wsm[ci*16 + kh*4 + kw];
                #pragma unroll
                for (int j = 0; j < 8; j++) FMA2(acc[j], v2, wr[j]);
            }
        }
    }
    float* outp = g_h1 + (size_t)n * 16 * 16384 + oh*128 + ow;
    #pragma unroll
    for (int j = 0; j < 8; j++){
        float2 f = unpack2(acc[j]);
        outp[(size_t)(2*j  ) * 16384] = f.x;
        outp[(size_t)(2*j+1) * 16384] = f.y;
    }
}

// ---------------- per-plane mean/var (instance norm stats) ------------------
__global__ __launch_bounds__(256) void k_stats(int mode){
    int p = blockIdx.x;
    const float* sp; float* mo; float* vo; int plane;
    if (mode == 0){ sp = g_h1 + (size_t)p*16384; mo = g_m1; vo = g_v1; plane = 16384; }
    else          { sp = g_enc + (size_t)p*4096; mo = g_m2; vo = g_v2; plane = 4096; }
    float s = 0.f, q = 0.f;
    const float4* sp4 = (const float4*)sp;
    for (int i = threadIdx.x; i < plane/4; i += 256){
        float4 xv = sp4[i];
        s += xv.x + xv.y + xv.z + xv.w;
        q = fmaf(xv.x, xv.x, fmaf(xv.y, xv.y, fmaf(xv.z, xv.z, fmaf(xv.w, xv.w, q))));
    }
    __shared__ float rsum[8], rsq[8];
    s = warpsum(s); q = warpsum(q);
    int wid = threadIdx.x >> 5, lane = threadIdx.x & 31;
    if (lane == 0){ rsum[wid] = s; rsq[wid] = q; }
    __syncthreads();
    if (threadIdx.x == 0){
        float S = 0.f, Q = 0.f;
        #pragma unroll
        for (int i = 0; i < 8; i++){ S += rsum[i]; Q += rsq[i]; }
        float inv = 1.f / (float)plane;
        float mm = S * inv;
        mo[p] = mm;
        vo[p] = Q * inv - mm*mm;
    }
}

// ---------------- in-place normalize + relu ---------------------------------
__global__ __launch_bounds__(256) void k_norm(int mode){
    int p = blockIdx.x;
    float* sp; float m, r; int plane;
    if (mode == 0){ sp = g_h1 + (size_t)p*16384; m = g_m1[p]; r = rsqrtf(g_v1[p] + EPSN); plane = 16384; }
    else          { sp = g_enc + (size_t)p*4096; m = g_m2[p]; r = rsqrtf(g_v2[p] + EPSN); plane = 4096; }
    float4* sp4 = (float4*)sp;
    for (int i = threadIdx.x; i < plane/4; i += 256){
        float4 xv = sp4[i];
        xv.x = fmaxf((xv.x - m) * r, 0.f);
        xv.y = fmaxf((xv.y - m) * r, 0.f);
        xv.z = fmaxf((xv.z - m) * r, 0.f);
        xv.w = fmaxf((xv.w - m) * r, 0.f);
        sp4[i] = xv;
    }
}

// ---------------- conv2: g_h1(normalized) -> g_enc[32,64,64,64] -------------
// block = 256 threads = 4 output rows x 64 cols; grid = 32 n x 16 row-tiles.
// smem: weights (16384 f) + input tile 16ci x 10 x 132 (21120 f)
__global__ __launch_bounds__(256) void k_conv2(const float* __restrict__ w,
                                               const float* __restrict__ b){
    float* wsm = dynsm;            // 16384 : (ci*16+kh*4+kw)*64 + co (pairs contig)
    float* tile = dynsm + 16384;   // 21120 : ci*1320 + r*132 + c
    int tid = threadIdx.x;
    for (int i = tid; i < 16384; i += 256){
        int co = i >> 8, idx = i & 255;
        wsm[idx*64 + co] = w[i];
    }
    int n   = blockIdx.x >> 4;
    int oh0 = (blockIdx.x & 15) << 2;
    int ihg0 = 2*oh0 - 1;
    const float* hn = g_h1 + (size_t)n * 16 * 16384;
    for (int i = tid; i < 16*10*132; i += 256){
        int ci = i / 1320, rem = i % 1320;
        int r = rem / 132, c = rem % 132;
        int ihg = ihg0 + r, iwg = c - 1;
        float v = 0.f;
        if ((unsigned)ihg < 128u && (unsigned)iwg < 128u)
            v = hn[(ci*128 + ihg)*128 + iwg];
        tile[i] = v;
    }
    __syncthreads();
    int ohl = tid >> 6, ow = tid & 63;
    ull acc[32];
    #pragma unroll
    for (int j = 0; j < 32; j++) acc[j] = pack2(b[2*j], b[2*j+1]);
    for (int ci = 0; ci < 16; ci++){
        const float* tci = tile + ci*1320;
        #pragma unroll
        for (int kh = 0; kh < 4; kh++){
            const float* trow = tci + (2*ohl + kh)*132 + 2*ow;
            #pragma unroll
            for (int kw = 0; kw < 4; kw++){
                float v = trow[kw];
                ull v2 = pack2(v, v);
                const ull* wr = (const ull*)(wsm + (ci*16 + kh*4 + kw)*64);
                #pragma unroll
                for (int j = 0; j < 32; j++) FMA2(acc[j], v2, wr[j]);
            }
        }
    }
    int oh = oh0 + ohl;
    float* outp = g_enc + (size_t)n * 64 * 4096 + oh*64 + ow;
    #pragma unroll
    for (int j = 0; j < 32; j++){
        float2 f = unpack2(acc[j]);
        outp[(size_t)(2*j  ) * 4096] = f.x;
        outp[(size_t)(2*j+1) * 4096] = f.y;
    }
}

// ---------------- RVQ: 6 stages, argmin + residual update + loss ------------
__global__ __launch_bounds__(512) void k_rvq(const float* __restrict__ cb_all){
    float* cbsm  = dynsm;             // 32768 (512x64)
    float* norms = dynsm + 32768;     // 512
    float* red   = norms + 512;       // 16
    int tid = threadIdx.x;
    int vec = blockIdx.x * 512 + tid;
    int n   = vec >> 12;
    int pix = vec & 4095;
    const float* encp = g_enc + (size_t)n * 64 * 4096 + pix;
    ull r2[32];
    #pragma unroll
    for (int d = 0; d < 32; d++)
        r2[d] = pack2(encp[(size_t)(2*d)*4096], encp[(size_t)(2*d+1)*4096]);
    float lossacc = 0.f;
    const ull NEG1 = pack2(-1.f, -1.f);

    for (int st = 0; st < 6; st++){
        __syncthreads();
        {
            const float4* src = (const float4*)(cb_all + (size_t)st * 32768);
            float4* dst = (float4*)cbsm;
            for (int i = tid; i < 8192; i += 512) dst[i] = src[i];
        }
        __syncthreads();
        if (tid < 512){
            const float4* rowp = (const float4*)(cbsm + tid*64);
            float s = 0.f;
            #pragma unroll
            for (int i = 0; i < 16; i++){
                float4 e = rowp[i];
                s = fmaf(e.x,e.x, fmaf(e.y,e.y, fmaf(e.z,e.z, fmaf(e.w,e.w, s))));
            }
            norms[tid] = s;
        }
        __syncthreads();
        float best = 3.4e38f; int bestk = 0;
        for (int k = 0; k < 512; k += 4){
            ull a0 = 0, a1 = 0, a2 = 0, a3 = 0;
            const ulonglong2* q0 = (const ulonglong2*)(cbsm + (k+0)*64);
            const ulonglong2* q1 = (const ulonglong2*)(cbsm + (k+1)*64);
            const ulonglong2* q2 = (const ulonglong2*)(cbsm + (k+2)*64);
            const ulonglong2* q3 = (const ulonglong2*)(cbsm + (k+3)*64);
            #pragma unroll
            for (int i = 0; i < 16; i++){
                ulonglong2 e0 = q0[i], e1 = q1[i], e2 = q2[i], e3 = q3[i];
                FMA2(a0, r2[2*i], e0.x); FMA2(a0, r2[2*i+1], e0.y);
                FMA2(a1, r2[2*i], e1.x); FMA2(a1, r2[2*i+1], e1.y);
                FMA2(a2, r2[2*i], e2.x); FMA2(a2, r2[2*i+1], e2.y);
                FMA2(a3, r2[2*i], e3.x); FMA2(a3, r2[2*i+1], e3.y);
            }
            float2 f0 = unpack2(a0), f1 = unpack2(a1), f2 = unpack2(a2), f3 = unpack2(a3);
            float s0 = fmaf(-2.f, f0.x + f0.y, norms[k+0]);
            float s1 = fmaf(-2.f, f1.x + f1.y, norms[k+1]);
            float s2 = fmaf(-2.f, f2.x + f2.y, norms[k+2]);
            float s3 = fmaf(-2.f, f3.x + f3.y, norms[k+3]);
            if (s0 < best){ best = s0; bestk = k; }
            if (s1 < best){ best = s1; bestk = k+1; }
            if (s2 < best){ best = s2; bestk = k+2; }
            if (s3 < best){ best = s3; bestk = k+3; }
        }
        const ulonglong2* qb = (const ulonglong2*)(cbsm + bestk*64);
        ull sq = 0;
        #pragma unroll
        for (int i = 0; i < 16; i++){
            ulonglong2 e = qb[i];
            FMA2(r2[2*i],   e.x, NEG1);
            FMA2(r2[2*i+1], e.y, NEG1);
            FMA2(sq, r2[2*i],   r2[2*i]);
            FMA2(sq, r2[2*i+1], r2[2*i+1]);
        }
        float2 fq = unpack2(sq);
        lossacc += fq.x + fq.y;
    }
    lossacc = warpsum(lossacc);
    int wid = tid >> 5, lane = tid & 31;
    if (lane == 0) red[wid] = lossacc;
    __syncthreads();
    if (tid == 0){
        float S = 0.f;
        #pragma unroll
        for (int i = 0; i < 16; i++) S += red[i];
        atomicAdd(&g_loss, S * (1.25f / (131072.f * 64.f)));
    }
    float* dp = g_dec_in + (size_t)n * 64 * 4096 + pix;
    #pragma unroll
    for (int d = 0; d < 32; d++){
        float2 rr = unpack2(r2[d]);
        dp[(size_t)(2*d  )*4096] = encp[(size_t)(2*d  )*4096] - rr.x;
        dp[(size_t)(2*d+1)*4096] = encp[(size_t)(2*d+1)*4096] - rr.y;
    }
}

// ---------------- deconv1: g_dec_in[32,64,64,64] -> g_d1[32,16,128,128] -----
__global__ __launch_bounds__(256) void k_deconv1(const float* __restrict__ w,
                                                 const float* __restrict__ b){
    float* wsm = dynsm;   // 16384 : (ci*16+kh*4+kw)*16 + co (pairs contig)
    int tid = threadIdx.x;
    for (int i = tid; i < 16384; i += 256){
        int co = i >> 10, idx = i & 1023;
        wsm[idx*16 + co] = w[i];
    }
    __syncthreads();
    int n   = blockIdx.x >> 6;
    int pos = ((blockIdx.x & 63) << 8) + tid;
    int oh = pos >> 7, ow = pos & 127;
    ull acc[8];
    #pragma unroll
    for (int j = 0; j < 8; j++) acc[j] = pack2(b[2*j], b[2*j+1]);
    int p = oh & 1, q = ow & 1;
    int ih0 = (oh + p - 2) >> 1, ih1 = (oh + p) >> 1;
    int iw0 = (ow + q - 2) >> 1, iw1 = (ow + q) >> 1;
    bool vh0 = (unsigned)ih0 < 64u, vh1 = (unsigned)ih1 < 64u;
    bool vw0 = (unsigned)iw0 < 64u, vw1 = (unsigned)iw1 < 64u;
    const float* din = g_dec_in + (size_t)n * 64 * 4096;
    for (int ci = 0; ci < 64; ci++){
        const float* pl = din + ci*4096;
        float v00 = (vh0 && vw0) ? pl[ih0*64 + iw0] : 0.f;
        float v01 = (vh0 && vw1) ? pl[ih0*64 + iw1] : 0.f;
        float v10 = (vh1 && vw0) ? pl[ih1*64 + iw0] : 0.f;
        float v11 = (vh1 && vw1) ? pl[ih1*64 + iw1] : 0.f;
        ull p00 = pack2(v00, v00), p01 = pack2(v01, v01);
        ull p10 = pack2(v10, v10), p11 = pack2(v11, v11);
        const ull* w00 = (const ull*)(wsm + (ci*16 + p*4     + q    )*16);
        const ull* w01 = (const ull*)(wsm + (ci*16 + p*4     + q + 2)*16);
        const ull* w10 = (const ull*)(wsm + (ci*16 + (p+2)*4 + q    )*16);
        const ull* w11 = (const ull*)(wsm + (ci*16 + (p+2)*4 + q + 2)*16);
        #pragma unroll
        for (int j = 0; j < 8; j++){
            FMA2(acc[j], p00, w00[j]);
            FMA2(acc[j], p01, w01[j]);
            FMA2(acc[j], p10, w10[j]);
            FMA2(acc[j], p11, w11[j]);
        }
    }
    float* outp = g_d1 + (size_t)n * 16 * 16384 + oh*128 + ow;
    #pragma unroll
    for (int j = 0; j < 8; j++){
        float2 f = unpack2(acc[j]);
        outp[(size_t)(2*j  ) * 16384] = f.x;
        outp[(size_t)(2*j+1) * 16384] = f.y;
    }
}

// ---------------- batchnorm stats over g_d1 (per channel, N*H*W) ------------
__global__ __launch_bounds__(256) void k_bnstats(){
    int c = blockIdx.x & 15, nn = blockIdx.x >> 4;
    const float4* sp = (const float4*)(g_d1 + (size_t)(nn*16 + c) * 16384);
    float s = 0.f, q = 0.f;
    for (int i = threadIdx.x; i < 4096; i += 256){
        float4 xv = sp[i];
        s += xv.x + xv.y + xv.z + xv.w;
        q = fmaf(xv.x, xv.x, fmaf(xv.y, xv.y, fmaf(xv.z, xv.z, fmaf(xv.w, xv.w, q))));
    }
    __shared__ float rsum[8], rsq[8];
    s = warpsum(s); q = warpsum(q);
    int wid = threadIdx.x >> 5, lane = threadIdx.x & 31;
    if (lane == 0){ rsum[wid] = s; rsq[wid] = q; }
    __syncthreads();
    if (threadIdx.x == 0){
        float S = 0.f, Q = 0.f;
        #pragma unroll
        for (int i = 0; i < 8; i++){ S += rsum[i]; Q += rsq[i]; }
        atomicAdd(&g_bn_s[c], S);
        atomicAdd(&g_bn_q[c], Q);
    }
}

// ---------------- deconv2: BN(g_d1) -> decoded[32,3,256,256] ----------------
__global__ __launch_bounds__(256) void k_deconv2(const float* __restrict__ w,
                                                 const float* __restrict__ b,
                                                 const float* __restrict__ gamma,
                                                 const float* __restrict__ beta,
                                                 float* __restrict__ out){
    __shared__ ull   wp[256];         // (co0,co1) pairs, idx = ci*16+kh*4+kw
    __shared__ float w2[256];         // co2
    __shared__ float Asm[16], Bsm[16];
    int tid = threadIdx.x;
    wp[tid] = pack2(w[tid], w[256 + tid]);
    w2[tid] = w[512 + tid];
    if (tid < 16){
        const float Nc = 32.f * 128.f * 128.f;
        float m = g_bn_s[tid] / Nc;
        float var = g_bn_q[tid] / Nc - m*m;
        float A = rsqrtf(var + EPSN) * gamma[tid];
        Asm[tid] = A;
        Bsm[tid] = fmaf(-m, A, beta[tid]);
    }
    __syncthreads();
    int n   = blockIdx.x >> 8;
    int pos = ((blockIdx.x & 255) << 8) + tid;
    int oh = pos >> 8, ow = pos & 255;
    ull acc01 = pack2(b[0], b[1]);
    float acc2 = b[2];
    int p = oh & 1, q = ow & 1;
    int ih0 = (oh + p - 2) >> 1, ih1 = (oh + p) >> 1;
    int iw0 = (ow + q - 2) >> 1, iw1 = (ow + q) >> 1;
    bool vh0 = (unsigned)ih0 < 128u, vh1 = (unsigned)ih1 < 128u;
    bool vw0 = (unsigned)iw0 < 128u, vw1 = (unsigned)iw1 < 128u;
    const float* din = g_d1 + (size_t)n * 16 * 16384;
    for (int ci = 0; ci < 16; ci++){
        const float* pl = din + ci*16384;
        float A = Asm[ci], Bv = Bsm[ci];
        float v00 = (vh0 && vw0) ? fmaf(pl[ih0*128 + iw0], A, Bv) : 0.f;
        float v01 = (vh0 && vw1) ? fmaf(pl[ih0*128 + iw1], A, Bv) : 0.f;
        float v10 = (vh1 && vw0) ? fmaf(pl[ih1*128 + iw0], A, Bv) : 0.f;
        float v11 = (vh1 && vw1) ? fmaf(pl[ih1*128 + iw1], A, Bv) : 0.f;
        int i00 = ci*16 + p*4 + q,     i01 = i00 + 2;
        int i10 = ci*16 + (p+2)*4 + q, i11 = i10 + 2;
        FMA2(acc01, pack2(v00,v00), wp[i00]);
        FMA2(acc01, pack2(v01,v01), wp[i01]);
        FMA2(acc01, pack2(v10,v10), wp[i10]);
        FMA2(acc01, pack2(v11,v11), wp[i11]);
        acc2 = fmaf(v00, w2[i00], fmaf(v01, w2[i01], fmaf(v10, w2[i10], fmaf(v11, w2[i11], acc2))));
    }
    float* outp = out + (size_t)n * 3 * 65536 + oh*256 + ow;
    float2 f01 = unpack2(acc01);
    outp[0]      = f01.x;
    outp[65536]  = f01.y;
    outp[131072] = acc2;
}

__global__ void k_write_loss(float* __restrict__ out, int idx){
    if (threadIdx.x == 0) out[idx] = g_loss;
}

// ---------------- launch -----------------------------------------------------
extern "C" void kernel_launch(void* const* d_in, const int* in_sizes, int n_in,
                              void* d_out, int out_size){
    const float* x     = (const float*)d_in[0];
    const float* ew1   = (const float*)d_in[1];
    const float* eb1   = (const float*)d_in[2];
    const float* ew2   = (const float*)d_in[3];
    const float* eb2   = (const float*)d_in[4];
    const float* cb    = (const float*)d_in[5];
    const float* dw1   = (const float*)d_in[6];
    const float* db1   = (const float*)d_in[7];
    const float* gamma = (const float*)d_in[8];
    const float* beta  = (const float*)d_in[9];
    const float* dw2   = (const float*)d_in[10];
    const float* db2   = (const float*)d_in[11];
    float* out = (float*)d_out;

    const int conv2_smem   = (16384 + 21120) * 4;   // 150016 B
    const int rvq_smem     = (32768 + 512 + 16) * 4;
    const int deconv1_smem = 16384 * 4;

    cudaFuncSetAttribute(k_conv2,   cudaFuncAttributeMaxDynamicSharedMemorySize, conv2_smem);
    cudaFuncSetAttribute(k_rvq,     cudaFuncAttributeMaxDynamicSharedMemorySize, rvq_smem);
    cudaFuncSetAttribute(k_deconv1, cudaFuncAttributeMaxDynamicSharedMemorySize, deconv1_smem);

    k_zero<<<1, 32>>>();
    k_conv1<<<2048, 256>>>(x, ew1, eb1);
    k_stats<<<512, 256>>>(0);
    k_norm<<<512, 256>>>(0);
    k_conv2<<<512, 256, conv2_smem>>>(ew2, eb2);
    k_stats<<<2048, 256>>>(1);
    k_norm<<<2048, 256>>>(1);
    k_rvq<<<256, 512, rvq_smem>>>(cb);
    k_deconv1<<<2048, 256, deconv1_smem>>>(dw1, db1);
    k_bnstats<<<512, 256>>>();
    k_deconv2<<<8192, 256>>>(dw2, db2, gamma, beta, out);
    k_write_loss<<<1, 32>>>(out, out_size - 1);
}

// round 3
// speedup vs baseline: 1.0236x; 1.0170x over previous
#include <cuda_runtime.h>

#define EPSN 1e-5f

// ---------------- scratch (device globals; no allocations allowed) ----------
__device__ float g_h1[32*16*128*128];     // conv1 output (normalized in-place)
__device__ float g_enc[32*64*64*64];      // conv2 output (normalized in-place)
__device__ float g_dec_in[32*64*64*64];   // quantized (flat - residual), NCHW
__device__ float g_d1[32*16*128*128];     // deconv1 raw output
__device__ float g_m1[512],  g_v1[512];   // instance-norm stats for h1 (n*16+c)
__device__ float g_m2[2048], g_v2[2048];  // instance-norm stats for enc (n*64+c)
__device__ float g_bn_s[16], g_bn_q[16];  // batchnorm sums
__device__ float g_loss;

extern __shared__ float dynsm[];

typedef unsigned long long ull;

// packed f32x2 fma: acc = a*b + acc (elementwise on both lanes)
#define FMA2(acc, a, b_) asm("fma.rn.f32x2 %0, %1, %2, %3;" : "=l"(acc) : "l"(a), "l"(b_), "l"(acc))

__device__ __forceinline__ float2 unpack2(ull p){
    float2 f; asm("mov.b64 {%0,%1}, %2;" : "=f"(f.x), "=f"(f.y) : "l"(p)); return f;
}
__device__ __forceinline__ ull pack2(float lo, float hi){
    ull p; asm("mov.b64 %0, {%1,%2};" : "=l"(p) : "f"(lo), "f"(hi)); return p;
}

__device__ __forceinline__ float warpsum(float v){
    #pragma unroll
    for (int o = 16; o; o >>= 1) v += __shfl_down_sync(0xffffffffu, v, o);
    return v;
}

// ---------------- zero accumulators ----------------------------------------
__global__ void k_zero(){
    int t = threadIdx.x;
    if (t == 0) g_loss = 0.f;
    if (t < 16){ g_bn_s[t] = 0.f; g_bn_q[t] = 0.f; }
}

// ---------------- conv1: x[32,3,256,256] -> g_h1[32,16,128,128] -------------
// 512 threads; each thread computes 2 pixels (oh, col) and (oh, col+64)
// sharing the same weight loads. grid = 32n x 16 chunks (8 rows each).
__global__ __launch_bounds__(512) void k_conv1(const float* __restrict__ x,
                                               const float* __restrict__ w,
                                               const float* __restrict__ b){
    __shared__ float wsm[48][16];
    int tid = threadIdx.x;
    for (int i = tid; i < 768; i += 512){
        int co = i / 48, idx = i % 48;
        wsm[idx][co] = w[i];
    }
    __syncthreads();
    int n     = blockIdx.x >> 4;
    int chunk = blockIdx.x & 15;
    int row = tid >> 6, col = tid & 63;
    int oh = chunk*8 + row;
    ull accA[8], accB[8];
    #pragma unroll
    for (int j = 0; j < 8; j++){ accA[j] = pack2(b[2*j], b[2*j+1]); accB[j] = accA[j]; }
    const float* xn = x + (size_t)n * 3 * 65536;
    for (int ci = 0; ci < 3; ci++){
        #pragma unroll
        for (int kh = 0; kh < 4; kh++){
            int ih = 2*oh + kh - 1;
            if ((unsigned)ih >= 256u) continue;
            const float* rowp = xn + (ci*256 + ih)*256;
            #pragma unroll
            for (int kw = 0; kw < 4; kw++){
                int iwA = 2*col + kw - 1;
                int iwB = iwA + 128;
                float vA = ((unsigned)iwA < 256u) ? rowp[iwA] : 0.f;
                float vB = ((unsigned)iwB < 256u) ? rowp[iwB] : 0.f;
                ull vA2 = pack2(vA, vA), vB2 = pack2(vB, vB);
                const ull* wr = (const ull*)wsm[ci*16 + kh*4 + kw];
                #pragma unroll
                for (int j = 0; j < 8; j++){
                    FMA2(accA[j], vA2, wr[j]);
                    FMA2(accB[j], vB2, wr[j]);
                }
            }
        }
    }
    float* outp = g_h1 + (size_t)n * 16 * 16384 + oh*128 + col;
    #pragma unroll
    for (int j = 0; j < 8; j++){
        float2 fA = unpack2(accA[j]), fB = unpack2(accB[j]);
        outp[(size_t)(2*j  ) * 16384]      = fA.x;
        outp[(size_t)(2*j+1) * 16384]      = fA.y;
        outp[(size_t)(2*j  ) * 16384 + 64] = fB.x;
        outp[(size_t)(2*j+1) * 16384 + 64] = fB.y;
    }
}

// ---------------- per-plane mean/var (instance norm stats), 512 thr ---------
__global__ __launch_bounds__(512) void k_stats(int mode){
    int p = blockIdx.x;
    const float* sp; float* mo; float* vo; int plane;
    if (mode == 0){ sp = g_h1 + (size_t)p*16384; mo = g_m1; vo = g_v1; plane = 16384; }
    else          { sp = g_enc + (size_t)p*4096; mo = g_m2; vo = g_v2; plane = 4096; }
    float s = 0.f, q = 0.f;
    const float4* sp4 = (const float4*)sp;
    for (int i = threadIdx.x; i < plane/4; i += 512){
        float4 xv = sp4[i];
        s += xv.x + xv.y + xv.z + xv.w;
        q = fmaf(xv.x, xv.x, fmaf(xv.y, xv.y, fmaf(xv.z, xv.z, fmaf(xv.w, xv.w, q))));
    }
    __shared__ float rsum[16], rsq[16];
    s = warpsum(s); q = warpsum(q);
    int wid = threadIdx.x >> 5, lane = threadIdx.x & 31;
    if (lane == 0){ rsum[wid] = s; rsq[wid] = q; }
    __syncthreads();
    if (threadIdx.x == 0){
        float S = 0.f, Q = 0.f;
        #pragma unroll
        for (int i = 0; i < 16; i++){ S += rsum[i]; Q += rsq[i]; }
        float inv = 1.f / (float)plane;
        float mm = S * inv;
        mo[p] = mm;
        vo[p] = Q * inv - mm*mm;
    }
}

// ---------------- in-place normalize + relu ---------------------------------
__global__ __launch_bounds__(512) void k_norm(int mode){
    int p = blockIdx.x;
    float* sp; float m, r; int plane;
    if (mode == 0){ sp = g_h1 + (size_t)p*16384; m = g_m1[p]; r = rsqrtf(g_v1[p] + EPSN); plane = 16384; }
    else          { sp = g_enc + (size_t)p*4096; m = g_m2[p]; r = rsqrtf(g_v2[p] + EPSN); plane = 4096; }
    float4* sp4 = (float4*)sp;
    for (int i = threadIdx.x; i < plane/4; i += 512){
        float4 xv = sp4[i];
        xv.x = fmaxf((xv.x - m) * r, 0.f);
        xv.y = fmaxf((xv.y - m) * r, 0.f);
        xv.z = fmaxf((xv.z - m) * r, 0.f);
        xv.w = fmaxf((xv.w - m) * r, 0.f);
        sp4[i] = xv;
    }
}

// ---------------- conv2: g_h1(normalized) -> g_enc[32,64,64,64] -------------
// 512 threads = 8 output rows x 64 cols; grid = 32n x 8 row-tiles.
// smem: weights (16384 f) + input tile 16ci x 18 x 132 (38016 f) = 217.6 KB
__global__ __launch_bounds__(512) void k_conv2(const float* __restrict__ w,
                                               const float* __restrict__ b){
    float* wsm = dynsm;            // 16384 : (ci*16+kh*4+kw)*64 + co (pairs contig)
    float* tile = dynsm + 16384;   // 38016 : ci*2376 + r*132 + c
    int tid = threadIdx.x;
    for (int i = tid; i < 16384; i += 512){
        int co = i >> 8, idx = i & 255;
        wsm[idx*64 + co] = w[i];
    }
    int n   = blockIdx.x >> 3;
    int oh0 = (blockIdx.x & 7) << 3;
    int ihg0 = 2*oh0 - 1;
    const float* hn = g_h1 + (size_t)n * 16 * 16384;
    for (int i = tid; i < 16*18*132; i += 512){
        int ci = i / 2376, rem = i % 2376;
        int r = rem / 132, c = rem % 132;
        int ihg = ihg0 + r, iwg = c - 1;
        float v = 0.f;
        if ((unsigned)ihg < 128u && (unsigned)iwg < 128u)
            v = hn[(ci*128 + ihg)*128 + iwg];
        tile[i] = v;
    }
    __syncthreads();
    int ohl = tid >> 6, ow = tid & 63;
    ull acc[32];
    #pragma unroll
    for (int j = 0; j < 32; j++) acc[j] = pack2(b[2*j], b[2*j+1]);
    for (int ci = 0; ci < 16; ci++){
        const float* tci = tile + ci*2376;
        #pragma unroll
        for (int kh = 0; kh < 4; kh++){
            const float* trow = tci + (2*ohl + kh)*132 + 2*ow;
            #pragma unroll
            for (int kw = 0; kw < 4; kw++){
                float v = trow[kw];
                ull v2 = pack2(v, v);
                const ull* wr = (const ull*)(wsm + (ci*16 + kh*4 + kw)*64);
                #pragma unroll
                for (int j = 0; j < 32; j++) FMA2(acc[j], v2, wr[j]);
            }
        }
    }
    int oh = oh0 + ohl;
    float* outp = g_enc + (size_t)n * 64 * 4096 + oh*64 + ow;
    #pragma unroll
    for (int j = 0; j < 32; j++){
        float2 f = unpack2(acc[j]);
        outp[(size_t)(2*j  ) * 4096] = f.x;
        outp[(size_t)(2*j+1) * 4096] = f.y;
    }
}

// ---------------- RVQ: 6 stages, argmin + residual update + loss ------------
__global__ __launch_bounds__(512) void k_rvq(const float* __restrict__ cb_all){
    float* cbsm  = dynsm;             // 32768 (512x64)
    float* norms = dynsm + 32768;     // 512
    float* red   = norms + 512;       // 16
    int tid = threadIdx.x;
    int vec = blockIdx.x * 512 + tid;
    int n   = vec >> 12;
    int pix = vec & 4095;
    const float* encp = g_enc + (size_t)n * 64 * 4096 + pix;
    ull r2[32];
    #pragma unroll
    for (int d = 0; d < 32; d++)
        r2[d] = pack2(encp[(size_t)(2*d)*4096], encp[(size_t)(2*d+1)*4096]);
    float lossacc = 0.f;
    const ull NEG1 = pack2(-1.f, -1.f);

    for (int st = 0; st < 6; st++){
        __syncthreads();
        {
            const float4* src = (const float4*)(cb_all + (size_t)st * 32768);
            float4* dst = (float4*)cbsm;
            for (int i = tid; i < 8192; i += 512) dst[i] = src[i];
        }
        __syncthreads();
        if (tid < 512){
            const float4* rowp = (const float4*)(cbsm + tid*64);
            float s = 0.f;
            #pragma unroll
            for (int i = 0; i < 16; i++){
                float4 e = rowp[i];
                s = fmaf(e.x,e.x, fmaf(e.y,e.y, fmaf(e.z,e.z, fmaf(e.w,e.w, s))));
            }
            norms[tid] = s;
        }
        __syncthreads();
        float best = 3.4e38f; int bestk = 0;
        for (int k = 0; k < 512; k += 4){
            ull a0 = 0, a1 = 0, a2 = 0, a3 = 0;
            const ulonglong2* q0 = (const ulonglong2*)(cbsm + (k+0)*64);
            const ulonglong2* q1 = (const ulonglong2*)(cbsm + (k+1)*64);
            const ulonglong2* q2 = (const ulonglong2*)(cbsm + (k+2)*64);
            const ulonglong2* q3 = (const ulonglong2*)(cbsm + (k+3)*64);
            #pragma unroll
            for (int i = 0; i < 16; i++){
                ulonglong2 e0 = q0[i], e1 = q1[i], e2 = q2[i], e3 = q3[i];
                FMA2(a0, r2[2*i], e0.x); FMA2(a0, r2[2*i+1], e0.y);
                FMA2(a1, r2[2*i], e1.x); FMA2(a1, r2[2*i+1], e1.y);
                FMA2(a2, r2[2*i], e2.x); FMA2(a2, r2[2*i+1], e2.y);
                FMA2(a3, r2[2*i], e3.x); FMA2(a3, r2[2*i+1], e3.y);
            }
            float2 f0 = unpack2(a0), f1 = unpack2(a1), f2 = unpack2(a2), f3 = unpack2(a3);
            float s0 = fmaf(-2.f, f0.x + f0.y, norms[k+0]);
            float s1 = fmaf(-2.f, f1.x + f1.y, norms[k+1]);
            float s2 = fmaf(-2.f, f2.x + f2.y, norms[k+2]);
            float s3 = fmaf(-2.f, f3.x + f3.y, norms[k+3]);
            if (s0 < best){ best = s0; bestk = k; }
            if (s1 < best){ best = s1; bestk = k+1; }
            if (s2 < best){ best = s2; bestk = k+2; }
            if (s3 < best){ best = s3; bestk = k+3; }
        }
        const ulonglong2* qb = (const ulonglong2*)(cbsm + bestk*64);
        ull sq = 0;
        #pragma unroll
        for (int i = 0; i < 16; i++){
            ulonglong2 e = qb[i];
            FMA2(r2[2*i],   e.x, NEG1);
            FMA2(r2[2*i+1], e.y, NEG1);
            FMA2(sq, r2[2*i],   r2[2*i]);
            FMA2(sq, r2[2*i+1], r2[2*i+1]);
        }
        float2 fq = unpack2(sq);
        lossacc += fq.x + fq.y;
    }
    lossacc = warpsum(lossacc);
    int wid = tid >> 5, lane = tid & 31;
    if (lane == 0) red[wid] = lossacc;
    __syncthreads();
    if (tid == 0){
        float S = 0.f;
        #pragma unroll
        for (int i = 0; i < 16; i++) S += red[i];
        atomicAdd(&g_loss, S * (1.25f / (131072.f * 64.f)));
    }
    float* dp = g_dec_in + (size_t)n * 64 * 4096 + pix;
    #pragma unroll
    for (int d = 0; d < 32; d++){
        float2 rr = unpack2(r2[d]);
        dp[(size_t)(2*d  )*4096] = encp[(size_t)(2*d  )*4096] - rr.x;
        dp[(size_t)(2*d+1)*4096] = encp[(size_t)(2*d+1)*4096] - rr.y;
    }
}

// ---------------- deconv1: g_dec_in[32,64,64,64] -> g_d1[32,16,128,128] -----
// 512 threads; 2 pixels per thread (oh,col) & (oh,col+64) — identical weights.
// grid = 32n x 16 chunks (8 rows each).
__global__ __launch_bounds__(512) void k_deconv1(const float* __restrict__ w,
                                                 const float* __restrict__ b){
    float* wsm = dynsm;   // 16384 : (ci*16+kh*4+kw)*16 + co (pairs contig)
    int tid = threadIdx.x;
    for (int i = tid; i < 16384; i += 512){
        int co = i >> 10, idx = i & 1023;
        wsm[idx*16 + co] = w[i];
    }
    __syncthreads();
    int n     = blockIdx.x >> 4;
    int chunk = blockIdx.x & 15;
    int row = tid >> 6, colA = tid & 63;
    int oh = chunk*8 + row;
    ull accA[8], accB[8];
    #pragma unroll
    for (int j = 0; j < 8; j++){ accA[j] = pack2(b[2*j], b[2*j+1]); accB[j] = accA[j]; }
    int p = oh & 1, q = colA & 1;
    int ih0 = (oh + p - 2) >> 1, ih1 = (oh + p) >> 1;
    int iwA0 = (colA + q - 2) >> 1, iwA1 = (colA + q) >> 1;
    int iwB0 = iwA0 + 32, iwB1 = iwA1 + 32;
    bool vh0 = (unsigned)ih0 < 64u, vh1 = (unsigned)ih1 < 64u;
    bool vwA0 = (unsigned)iwA0 < 64u;           // iwA1 always valid
    bool vwB1 = (unsigned)iwB1 < 64u;           // iwB0 always valid
    const float* din = g_dec_in + (size_t)n * 64 * 4096;
    const int i00 = p*4 + q, i01 = p*4 + q + 2, i10 = (p+2)*4 + q, i11 = (p+2)*4 + q + 2;
    for (int ci = 0; ci < 64; ci++){
        const float* pl = din + ci*4096;
        float vA00 = (vh0 && vwA0) ? pl[ih0*64 + iwA0] : 0.f;
        float vA01 = (vh0        ) ? pl[ih0*64 + iwA1] : 0.f;
        float vA10 = (vh1 && vwA0) ? pl[ih1*64 + iwA0] : 0.f;
        float vA11 = (vh1        ) ? pl[ih1*64 + iwA1] : 0.f;
        float vB00 = (vh0        ) ? pl[ih0*64 + iwB0] : 0.f;
        float vB01 = (vh0 && vwB1) ? pl[ih0*64 + iwB1] : 0.f;
        float vB10 = (vh1        ) ? pl[ih1*64 + iwB0] : 0.f;
        float vB11 = (vh1 && vwB1) ? pl[ih1*64 + iwB1] : 0.f;
        ull pA00 = pack2(vA00, vA00), pA01 = pack2(vA01, vA01);
        ull pA10 = pack2(vA10, vA10), pA11 = pack2(vA11, vA11);
        ull pB00 = pack2(vB00, vB00), pB01 = pack2(vB01, vB01);
        ull pB10 = pack2(vB10, vB10), pB11 = pack2(vB11, vB11);
        const ull* w00 = (const ull*)(wsm + (ci*16 + i00)*16);
        const ull* w01 = (const ull*)(wsm + (ci*16 + i01)*16);
        const ull* w10 = (const ull*)(wsm + (ci*16 + i10)*16);
        const ull* w11 = (const ull*)(wsm + (ci*16 + i11)*16);
        #pragma unroll
        for (int j = 0; j < 8; j++){
            ull a = w00[j], bb = w01[j], c = w10[j], d = w11[j];
            FMA2(accA[j], pA00, a); FMA2(accB[j], pB00, a);
            FMA2(accA[j], pA01, bb); FMA2(accB[j], pB01, bb);
            FMA2(accA[j], pA10, c); FMA2(accB[j], pB10, c);
            FMA2(accA[j], pA11, d); FMA2(accB[j], pB11, d);
        }
    }
    float* outp = g_d1 + (size_t)n * 16 * 16384 + oh*128 + colA;
    #pragma unroll
    for (int j = 0; j < 8; j++){
        float2 fA = unpack2(accA[j]), fB = unpack2(accB[j]);
        outp[(size_t)(2*j  ) * 16384]      = fA.x;
        outp[(size_t)(2*j+1) * 16384]      = fA.y;
        outp[(size_t)(2*j  ) * 16384 + 64] = fB.x;
        outp[(size_t)(2*j+1) * 16384 + 64] = fB.y;
    }
}

// ---------------- batchnorm stats over g_d1 (per channel, N*H*W) ------------
__global__ __launch_bounds__(256) void k_bnstats(){
    int c = blockIdx.x & 15, nn = blockIdx.x >> 4;
    const float4* sp = (const float4*)(g_d1 + (size_t)(nn*16 + c) * 16384);
    float s = 0.f, q = 0.f;
    for (int i = threadIdx.x; i < 4096; i += 256){
        float4 xv = sp[i];
        s += xv.x + xv.y + xv.z + xv.w;
        q = fmaf(xv.x, xv.x, fmaf(xv.y, xv.y, fmaf(xv.z, xv.z, fmaf(xv.w, xv.w, q))));
    }
    __shared__ float rsum[8], rsq[8];
    s = warpsum(s); q = warpsum(q);
    int wid = threadIdx.x >> 5, lane = threadIdx.x & 31;
    if (lane == 0){ rsum[wid] = s; rsq[wid] = q; }
    __syncthreads();
    if (threadIdx.x == 0){
        float S = 0.f, Q = 0.f;
        #pragma unroll
        for (int i = 0; i < 8; i++){ S += rsum[i]; Q += rsq[i]; }
        atomicAdd(&g_bn_s[c], S);
        atomicAdd(&g_bn_q[c], Q);
    }
}

// ---------------- deconv2: BN(g_d1) -> decoded[32,3,256,256] ----------------
// 512 threads; 2 pixels per thread (oh,col) & (oh,col+128) — identical weights.
// grid = 32n x 64 chunks (4 rows each).
__global__ __launch_bounds__(512) void k_deconv2(const float* __restrict__ w,
                                                 const float* __restrict__ b,
                                                 const float* __restrict__ gamma,
                                                 const float* __restrict__ beta,
                                                 float* __restrict__ out){
    __shared__ ull   wp[256];         // (co0,co1) pairs, idx = ci*16+kh*4+kw
    __shared__ float w2[256];         // co2
    __shared__ float Asm[16], Bsm[16];
    int tid = threadIdx.x;
    if (tid < 256){
        wp[tid] = pack2(w[tid], w[256 + tid]);
        w2[tid] = w[512 + tid];
    }
    if (tid < 16){
        const float Nc = 32.f * 128.f * 128.f;
        float m = g_bn_s[tid] / Nc;
        float var = g_bn_q[tid] / Nc - m*m;
        float A = rsqrtf(var + EPSN) * gamma[tid];
        Asm[tid] = A;
        Bsm[tid] = fmaf(-m, A, beta[tid]);
    }
    __syncthreads();
    int n     = blockIdx.x >> 6;
    int chunk = blockIdx.x & 63;
    int row = tid >> 7, colA = tid & 127;
    int oh = chunk*4 + row;
    ull accA01 = pack2(b[0], b[1]), accB01 = accA01;
    float accA2 = b[2], accB2 = b[2];
    int p = oh & 1, q = colA & 1;
    int ih0 = (oh + p - 2) >> 1, ih1 = (oh + p) >> 1;
    int iwA0 = (colA + q - 2) >> 1, iwA1 = (colA + q) >> 1;
    int iwB0 = iwA0 + 64, iwB1 = iwA1 + 64;
    bool vh0 = (unsigned)ih0 < 128u, vh1 = (unsigned)ih1 < 128u;
    bool vwA0 = (unsigned)iwA0 < 128u;            // iwA1 always valid
    bool vwB1 = (unsigned)iwB1 < 128u;            // iwB0 always valid
    const int i00 = p*4 + q, i01 = p*4 + q + 2, i10 = (p+2)*4 + q, i11 = (p+2)*4 + q + 2;
    const float* din = g_d1 + (size_t)n * 16 * 16384;
    for (int ci = 0; ci < 16; ci++){
        const float* pl = din + ci*16384;
        float A = Asm[ci], Bv = Bsm[ci];
        float vA00 = (vh0 && vwA0) ? fmaf(pl[ih0*128 + iwA0], A, Bv) : 0.f;
        float vA01 = (vh0        ) ? fmaf(pl[ih0*128 + iwA1], A, Bv) : 0.f;
        float vA10 = (vh1 && vwA0) ? fmaf(pl[ih1*128 + iwA0], A, Bv) : 0.f;
        float vA11 = (vh1        ) ? fmaf(pl[ih1*128 + iwA1], A, Bv) : 0.f;
        float vB00 = (vh0        ) ? fmaf(pl[ih0*128 + iwB0], A, Bv) : 0.f;
        float vB01 = (vh0 && vwB1) ? fmaf(pl[ih0*128 + iwB1], A, Bv) : 0.f;
        float vB10 = (vh1        ) ? fmaf(pl[ih1*128 + iwB0], A, Bv) : 0.f;
        float vB11 = (vh1 && vwB1) ? fmaf(pl[ih1*128 + iwB1], A, Bv) : 0.f;
        ull wa = wp[ci*16 + i00], wb = wp[ci*16 + i01];
        ull wc = wp[ci*16 + i10], wd = wp[ci*16 + i11];
        FMA2(accA01, pack2(vA00,vA00), wa); FMA2(accB01, pack2(vB00,vB00), wa);
        FMA2(accA01, pack2(vA01,vA01), wb); FMA2(accB01, pack2(vB01,vB01), wb);
        FMA2(accA01, pack2(vA10,vA10), wc); FMA2(accB01, pack2(vB10,vB10), wc);
        FMA2(accA01, pack2(vA11,vA11), wd); FMA2(accB01, pack2(vB11,vB11), wd);
        float s2a = w2[ci*16 + i00], s2b = w2[ci*16 + i01];
        float s2c = w2[ci*16 + i10], s2d = w2[ci*16 + i11];
        accA2 = fmaf(vA00, s2a, fmaf(vA01, s2b, fmaf(vA10, s2c, fmaf(vA11, s2d, accA2))));
        accB2 = fmaf(vB00, s2a, fmaf(vB01, s2b, fmaf(vB10, s2c, fmaf(vB11, s2d, accB2))));
    }
    float* outp = out + (size_t)n * 3 * 65536 + oh*256 + colA;
    float2 fA = unpack2(accA01), fB = unpack2(accB01);
    outp[0]            = fA.x;
    outp[65536]        = fA.y;
    outp[131072]       = accA2;
    outp[128]          = fB.x;
    outp[65536 + 128]  = fB.y;
    outp[131072 + 128] = accB2;
}

__global__ void k_write_loss(float* __restrict__ out, int idx){
    if (threadIdx.x == 0) out[idx] = g_loss;
}

// ---------------- launch -----------------------------------------------------
extern "C" void kernel_launch(void* const* d_in, const int* in_sizes, int n_in,
                              void* d_out, int out_size){
    const float* x     = (const float*)d_in[0];
    const float* ew1   = (const float*)d_in[1];
    const float* eb1   = (const float*)d_in[2];
    const float* ew2   = (const float*)d_in[3];
    const float* eb2   = (const float*)d_in[4];
    const float* cb    = (const float*)d_in[5];
    const float* dw1   = (const float*)d_in[6];
    const float* db1   = (const float*)d_in[7];
    const float* gamma = (const float*)d_in[8];
    const float* beta  = (const float*)d_in[9];
    const float* dw2   = (const float*)d_in[10];
    const float* db2   = (const float*)d_in[11];
    float* out = (float*)d_out;

    const int conv2_smem   = (16384 + 16*18*132) * 4;   // 217600 B
    const int rvq_smem     = (32768 + 512 + 16) * 4;
    const int deconv1_smem = 16384 * 4;

    cudaFuncSetAttribute(k_conv2,   cudaFuncAttributeMaxDynamicSharedMemorySize, conv2_smem);
    cudaFuncSetAttribute(k_rvq,     cudaFuncAttributeMaxDynamicSharedMemorySize, rvq_smem);
    cudaFuncSetAttribute(k_deconv1, cudaFuncAttributeMaxDynamicSharedMemorySize, deconv1_smem);

    k_zero<<<1, 32>>>();
    k_conv1<<<512, 512>>>(x, ew1, eb1);
    k_stats<<<512, 512>>>(0);
    k_norm<<<512, 512>>>(0);
    k_conv2<<<256, 512, conv2_smem>>>(ew2, eb2);
    k_stats<<<2048, 512>>>(1);
    k_norm<<<2048, 512>>>(1);
    k_rvq<<<256, 512, rvq_smem>>>(cb);
    k_deconv1<<<512, 512, deconv1_smem>>>(dw1, db1);
    k_bnstats<<<512, 256>>>();
    k_deconv2<<<2048, 512>>>(dw2, db2, gamma, beta, out);
    k_write_loss<<<1, 32>>>(out, out_size - 1);
}

// round 5
// speedup vs baseline: 1.0729x; 1.0482x over previous
#include <cuda_runtime.h>
#include <cuda_bf16.h>
#include <cuda_fp16.h>
#include <cstdint>

#define EPSN 1e-5f

// ---------------- scratch (device globals; no allocations allowed) ----------
__device__ float g_h1[32*16*128*128];     // conv1 output (normalized in-place)
__device__ float g_enc[32*64*64*64];      // conv2 output (normalized in-place)
__device__ float g_dec_in[32*64*64*64];   // quantized (flat - residual), NCHW
__device__ float g_d1[32*16*128*128];     // deconv1 raw output
__device__ float g_m1[512],  g_v1[512];   // instance-norm stats for h1
__device__ float g_m2[2048], g_v2[2048];  // instance-norm stats for enc
__device__ float g_bn_s[16], g_bn_q[16];  // batchnorm sums
__device__ float g_loss;
__device__ __nv_bfloat16 g_cb_bf16[6*512*64];  // bf16 codebooks
__device__ float g_cbnorm[6*512];              // fp32 |e|^2 per code
__device__ float g_bmax[6];                    // max |e| per stage

extern __shared__ float dynsm[];

typedef unsigned long long ull;

#define FMA2(acc, a, b_) asm("fma.rn.f32x2 %0, %1, %2, %3;" : "=l"(acc) : "l"(a), "l"(b_), "l"(acc))

__device__ __forceinline__ float2 unpack2(ull p){
    float2 f; asm("mov.b64 {%0,%1}, %2;" : "=f"(f.x), "=f"(f.y) : "l"(p)); return f;
}
__device__ __forceinline__ ull pack2(float lo, float hi){
    ull p; asm("mov.b64 %0, {%1,%2};" : "=l"(p) : "f"(lo), "f"(hi)); return p;
}
__device__ __forceinline__ float warpsum(float v){
    #pragma unroll
    for (int o = 16; o; o >>= 1) v += __shfl_down_sync(0xffffffffu, v, o);
    return v;
}
__device__ __forceinline__ uint32_t smem_u32(const void* p){
    uint32_t a;
    asm("{ .reg .u64 t; cvta.to.shared.u64 t, %1; cvt.u32.u64 %0, t; }" : "=r"(a) : "l"(p));
    return a;
}

#define SWZ128(b) ((b) ^ (((b) >> 3) & 0x70))

// m16n8k16 bf16 mma, fp32 accumulate
__device__ __forceinline__ void mma16816(float c[4], const uint32_t a[4],
                                         uint32_t b0, uint32_t b1){
    asm volatile(
        "mma.sync.aligned.m16n8k16.row.col.f32.bf16.bf16.f32 "
        "{%0,%1,%2,%3}, {%4,%5,%6,%7}, {%8,%9}, {%0,%1,%2,%3};"
        : "+f"(c[0]), "+f"(c[1]), "+f"(c[2]), "+f"(c[3])
        : "r"(a[0]), "r"(a[1]), "r"(a[2]), "r"(a[3]), "r"(b0), "r"(b1));
}
__device__ __forceinline__ void ldsm_x4(uint32_t r[4], uint32_t addr){
    asm volatile("ldmatrix.sync.aligned.m8n8.x4.shared.b16 {%0,%1,%2,%3}, [%4];"
        : "=r"(r[0]), "=r"(r[1]), "=r"(r[2]), "=r"(r[3]) : "r"(addr));
}

// ---------------- zero accumulators ----------------------------------------
__global__ void k_zero(){
    int t = threadIdx.x;
    if (t == 0) g_loss = 0.f;
    if (t < 16){ g_bn_s[t] = 0.f; g_bn_q[t] = 0.f; }
}

// ---------------- codebook prep: bf16 convert + norms + max norm ------------
__global__ __launch_bounds__(512) void k_cbprep(const float* __restrict__ cb){
    int st = blockIdx.x, k = threadIdx.x;
    const float* row = cb + (size_t)(st*512 + k) * 64;
    float s = 0.f;
    __nv_bfloat162* dst = (__nv_bfloat162*)g_cb_bf16 + (size_t)(st*512 + k) * 32;
    #pragma unroll
    for (int j = 0; j < 32; j++){
        float a = row[2*j], b = row[2*j+1];
        s = fmaf(a, a, fmaf(b, b, s));
        dst[j] = __float22bfloat162_rn(make_float2(a, b));
    }
    g_cbnorm[st*512 + k] = s;
    __shared__ float mx[16];
    float m = s;
    #pragma unroll
    for (int o = 16; o; o >>= 1) m = fmaxf(m, __shfl_down_sync(0xffffffffu, m, o));
    int wid = k >> 5;
    if ((k & 31) == 0) mx[wid] = m;
    __syncthreads();
    if (k == 0){
        float M = 0.f;
        #pragma unroll
        for (int i = 0; i < 16; i++) M = fmaxf(M, mx[i]);
        g_bmax[st] = sqrtf(M);
    }
}

// ---------------- conv1 ------------------------------------------------------
__global__ __launch_bounds__(512) void k_conv1(const float* __restrict__ x,
                                               const float* __restrict__ w,
                                               const float* __restrict__ b){
    __shared__ float wsm[48][16];
    int tid = threadIdx.x;
    for (int i = tid; i < 768; i += 512){
        int co = i / 48, idx = i % 48;
        wsm[idx][co] = w[i];
    }
    __syncthreads();
    int n     = blockIdx.x >> 4;
    int chunk = blockIdx.x & 15;
    int row = tid >> 6, col = tid & 63;
    int oh = chunk*8 + row;
    ull accA[8], accB[8];
    #pragma unroll
    for (int j = 0; j < 8; j++){ accA[j] = pack2(b[2*j], b[2*j+1]); accB[j] = accA[j]; }
    const float* xn = x + (size_t)n * 3 * 65536;
    for (int ci = 0; ci < 3; ci++){
        #pragma unroll
        for (int kh = 0; kh < 4; kh++){
            int ih = 2*oh + kh - 1;
            if ((unsigned)ih >= 256u) continue;
            const float* rowp = xn + (ci*256 + ih)*256;
            #pragma unroll
            for (int kw = 0; kw < 4; kw++){
                int iwA = 2*col + kw - 1;
                int iwB = iwA + 128;
                float vA = ((unsigned)iwA < 256u) ? rowp[iwA] : 0.f;
                float vB = ((unsigned)iwB < 256u) ? rowp[iwB] : 0.f;
                ull vA2 = pack2(vA, vA), vB2 = pack2(vB, vB);
                const ull* wr = (const ull*)wsm[ci*16 + kh*4 + kw];
                #pragma unroll
                for (int j = 0; j < 8; j++){
                    FMA2(accA[j], vA2, wr[j]);
                    FMA2(accB[j], vB2, wr[j]);
                }
            }
        }
    }
    float* outp = g_h1 + (size_t)n * 16 * 16384 + oh*128 + col;
    #pragma unroll
    for (int j = 0; j < 8; j++){
        float2 fA = unpack2(accA[j]), fB = unpack2(accB[j]);
        outp[(size_t)(2*j  ) * 16384]      = fA.x;
        outp[(size_t)(2*j+1) * 16384]      = fA.y;
        outp[(size_t)(2*j  ) * 16384 + 64] = fB.x;
        outp[(size_t)(2*j+1) * 16384 + 64] = fB.y;
    }
}

// ---------------- per-plane mean/var ----------------------------------------
__global__ __launch_bounds__(512) void k_stats(int mode){
    int p = blockIdx.x;
    const float* sp; float* mo; float* vo; int plane;
    if (mode == 0){ sp = g_h1 + (size_t)p*16384; mo = g_m1; vo = g_v1; plane = 16384; }
    else          { sp = g_enc + (size_t)p*4096; mo = g_m2; vo = g_v2; plane = 4096; }
    float s = 0.f, q = 0.f;
    const float4* sp4 = (const float4*)sp;
    for (int i = threadIdx.x; i < plane/4; i += 512){
        float4 xv = sp4[i];
        s += xv.x + xv.y + xv.z + xv.w;
        q = fmaf(xv.x, xv.x, fmaf(xv.y, xv.y, fmaf(xv.z, xv.z, fmaf(xv.w, xv.w, q))));
    }
    __shared__ float rsum[16], rsq[16];
    s = warpsum(s); q = warpsum(q);
    int wid = threadIdx.x >> 5, lane = threadIdx.x & 31;
    if (lane == 0){ rsum[wid] = s; rsq[wid] = q; }
    __syncthreads();
    if (threadIdx.x == 0){
        float S = 0.f, Q = 0.f;
        #pragma unroll
        for (int i = 0; i < 16; i++){ S += rsum[i]; Q += rsq[i]; }
        float inv = 1.f / (float)plane;
        float mm = S * inv;
        mo[p] = mm;
        vo[p] = Q * inv - mm*mm;
    }
}

// ---------------- in-place normalize + relu ---------------------------------
__global__ __launch_bounds__(512) void k_norm(int mode){
    int p = blockIdx.x;
    float* sp; float m, r; int plane;
    if (mode == 0){ sp = g_h1 + (size_t)p*16384; m = g_m1[p]; r = rsqrtf(g_v1[p] + EPSN); plane = 16384; }
    else          { sp = g_enc + (size_t)p*4096; m = g_m2[p]; r = rsqrtf(g_v2[p] + EPSN); plane = 4096; }
    float4* sp4 = (float4*)sp;
    for (int i = threadIdx.x; i < plane/4; i += 512){
        float4 xv = sp4[i];
        xv.x = fmaxf((xv.x - m) * r, 0.f);
        xv.y = fmaxf((xv.y - m) * r, 0.f);
        xv.z = fmaxf((xv.z - m) * r, 0.f);
        xv.w = fmaxf((xv.w - m) * r, 0.f);
        sp4[i] = xv;
    }
}

// ---------------- conv2 ------------------------------------------------------
__global__ __launch_bounds__(512) void k_conv2(const float* __restrict__ w,
                                               const float* __restrict__ b){
    float* wsm = dynsm;            // 16384
    float* tile = dynsm + 16384;   // 38016 : ci*2376 + r*132 + c
    int tid = threadIdx.x;
    for (int i = tid; i < 16384; i += 512){
        int co = i >> 8, idx = i & 255;
        wsm[idx*64 + co] = w[i];
    }
    int n   = blockIdx.x >> 3;
    int oh0 = (blockIdx.x & 7) << 3;
    int ihg0 = 2*oh0 - 1;
    const float* hn = g_h1 + (size_t)n * 16 * 16384;
    for (int i = tid; i < 16*18*132; i += 512){
        int ci = i / 2376, rem = i % 2376;
        int r = rem / 132, c = rem % 132;
        int ihg = ihg0 + r, iwg = c - 1;
        float v = 0.f;
        if ((unsigned)ihg < 128u && (unsigned)iwg < 128u)
            v = hn[(ci*128 + ihg)*128 + iwg];
        tile[i] = v;
    }
    __syncthreads();
    int ohl = tid >> 6, ow = tid & 63;
    ull acc[32];
    #pragma unroll
    for (int j = 0; j < 32; j++) acc[j] = pack2(b[2*j], b[2*j+1]);
    for (int ci = 0; ci < 16; ci++){
        const float* tci = tile + ci*2376;
        #pragma unroll
        for (int kh = 0; kh < 4; kh++){
            const float* trow = tci + (2*ohl + kh)*132 + 2*ow;
            #pragma unroll
            for (int kw = 0; kw < 4; kw++){
                float v = trow[kw];
                ull v2 = pack2(v, v);
                const ull* wr = (const ull*)(wsm + (ci*16 + kh*4 + kw)*64);
                #pragma unroll
                for (int j = 0; j < 32; j++) FMA2(acc[j], v2, wr[j]);
            }
        }
    }
    int oh = oh0 + ohl;
    float* outp = g_enc + (size_t)n * 64 * 4096 + oh*64 + ow;
    #pragma unroll
    for (int j = 0; j < 32; j++){
        float2 f = unpack2(acc[j]);
        outp[(size_t)(2*j  ) * 4096] = f.x;
        outp[(size_t)(2*j+1) * 4096] = f.y;
    }
}

// ---------------- RVQ via warp MMA (HMMA bf16) -------------------------------
// 1024 blocks x 128 threads; thread t owns vector t of its 128-vector tile.
// smem bytes:
//   [0, 65536)        codebook bf16 512x64, 128B rows, SW128-swizzled
//   [65536, 81920)    A tile bf16 128x64, SW128-swizzled
//   [81920, 83968)    norms fp32 [512]
//   [83968, 217088)   scores half, 128 rows x 520 (stride 1040 B)
#define CB_OFF   0
#define A_OFF    65536
#define NORM_OFF 81920
#define SC_OFF   83968
#define RVQ_SMEM 217088

__global__ __launch_bounds__(128) void k_rvq_mma(const float* __restrict__ cb){
    char* smc = (char*)dynsm;
    float* norms_sm = (float*)(smc + NORM_OFF);
    uint32_t sb = smem_u32(smc);
    int tid = threadIdx.x;
    int w = tid >> 5, l = tid & 31;
    int g = l >> 2, tig = l & 3;

    int n   = blockIdx.x >> 5;
    int pix = ((blockIdx.x & 31) << 7) + tid;
    const float* encp = g_enc + (size_t)n * 64 * 4096 + pix;

    float r[64];
    float rnorm2 = 0.f;
    #pragma unroll
    for (int c = 0; c < 64; c++){
        r[c] = encp[(size_t)c * 4096];
        rnorm2 = fmaf(r[c], r[c], rnorm2);
    }
    float lossacc = 0.f;

    for (int st = 0; st < 6; st++){
        // ---- cooperative cb load (bf16, swizzled) + norms ----
        {
            const uint4* csrc = (const uint4*)(g_cb_bf16 + (size_t)st * 32768);
            for (int i = tid; i < 4096; i += 128){
                int code = i >> 3, cc = i & 7;
                uint32_t byte = (uint32_t)code*128 + cc*16;
                *(uint4*)(smc + CB_OFF + (byte ^ ((code & 7) << 4))) = csrc[i];
            }
            #pragma unroll
            for (int i = tid; i < 512; i += 128)
                norms_sm[i] = g_cbnorm[st*512 + i];
        }
        // ---- write own residual row as bf16 (swizzled) ----
        #pragma unroll
        for (int j = 0; j < 32; j++){
            __nv_bfloat162 v = __float22bfloat162_rn(make_float2(r[2*j], r[2*j+1]));
            uint32_t byte = (uint32_t)tid*128 + j*4;
            *(uint32_t*)(smc + A_OFF + SWZ128(byte)) = *(uint32_t*)&v;
        }
        __syncthreads();

        // ---- MMA phase: warp w computes codes [w*128, w*128+128) x all 128 rows
        {
            // A ldmatrix lane address components
            int arow_lo = (l & 7) + ((l >> 3) & 1) * 8;   // + m*16
            int akb     = ((l >> 4) & 1) * 16;            // + k*32
            // B ldmatrix lane address components
            int t4 = l >> 3;
            int brow_lo = ((t4 >> 1) & 1) * 8 + (l & 7);  // + code base
            int bkb     = (t4 & 1) * 16;                  // + k*32

            for (int m = 0; m < 8; m++){
                uint32_t afr[4][4];
                #pragma unroll
                for (int k = 0; k < 4; k++){
                    uint32_t byte = (uint32_t)(m*16 + arow_lo)*128 + (k*32 + akb);
                    ldsm_x4(afr[k], sb + A_OFF + SWZ128(byte));
                }
                for (int ch = 0; ch < 8; ch++){
                    int nbase = w*128 + ch*16;
                    uint32_t bfr[4][4];
                    #pragma unroll
                    for (int k = 0; k < 4; k++){
                        uint32_t byte = (uint32_t)(nbase + brow_lo)*128 + (k*32 + bkb);
                        ldsm_x4(bfr[k], sb + CB_OFF + SWZ128(byte));
                    }
                    float clo[4] = {0.f,0.f,0.f,0.f};
                    float chi[4] = {0.f,0.f,0.f,0.f};
                    #pragma unroll
                    for (int k = 0; k < 4; k++){
                        mma16816(clo, afr[k], bfr[k][0], bfr[k][1]);
                        mma16816(chi, afr[k], bfr[k][2], bfr[k][3]);
                    }
                    // scores: s = norm - 2*dot, stored half
                    int col0 = nbase + tig*2;          // lo n8 cols
                    int col1 = col0 + 8;               // hi n8 cols
                    float2 nm0 = *(float2*)(norms_sm + col0);
                    float2 nm1 = *(float2*)(norms_sm + col1);
                    int row0 = m*16 + g;
                    char* p0 = smc + SC_OFF + (size_t)row0*1040;
                    char* p1 = p0 + 8*1040;
                    float s00 = fmaf(-2.f, clo[0], nm0.x);
                    float s01 = fmaf(-2.f, clo[1], nm0.y);
                    float s10 = fmaf(-2.f, clo[2], nm0.x);
                    float s11 = fmaf(-2.f, clo[3], nm0.y);
                    float t00 = fmaf(-2.f, chi[0], nm1.x);
                    float t01 = fmaf(-2.f, chi[1], nm1.y);
                    float t10 = fmaf(-2.f, chi[2], nm1.x);
                    float t11 = fmaf(-2.f, chi[3], nm1.y);
                    *(__half2*)(p0 + col0*2) = __floats2half2_rn(s00, s01);
                    *(__half2*)(p1 + col0*2) = __floats2half2_rn(s10, s11);
                    *(__half2*)(p0 + col1*2) = __floats2half2_rn(t00, t01);
                    *(__half2*)(p1 + col1*2) = __floats2half2_rn(t10, t11);
                }
            }
        }
        __syncthreads();

        // ---- per-row scan: min1/min2 + idx over 512 half scores ----
        const __half2* srow = (const __half2*)(smc + SC_OFF + (size_t)tid*1040);
        float mn1 = 3.4e38f, mn2 = 3.4e38f; int idx = 0;
        #pragma unroll 4
        for (int i = 0; i < 256; i++){
            float2 s = __half22float2(srow[i]);
            if (s.x < mn1){ mn2 = mn1; mn1 = s.x; idx = 2*i; }
            else if (s.x < mn2) mn2 = s.x;
            if (s.y < mn1){ mn2 = mn1; mn1 = s.y; idx = 2*i+1; }
            else if (s.y < mn2) mn2 = s.y;
        }
        // ---- margin + exact rescore of near-ties ----
        float srn  = sqrtf(rnorm2);
        float bmax = g_bmax[st];
        float margin = fmaf(0.0157f*srn, bmax,
                       fmaf(5e-4f, fmaf(2.f*srn, bmax, bmax*bmax), 1e-3f));
        int bestk = idx;
        bool need = (mn2 - mn1) <= 2.f * margin;
        if (__any_sync(0xffffffffu, need)){
            float thresh = mn1 + 2.f * margin;
            if (need){
                float bex = 3.4e38f; int bk = idx;
                for (int i = 0; i < 256; i++){
                    float2 s = __half22float2(srow[i]);
                    #pragma unroll
                    for (int half = 0; half < 2; half++){
                        float sv = half ? s.y : s.x;
                        if (sv <= thresh){
                            int k = 2*i + half;
                            const float4* ep = (const float4*)(cb + (size_t)st*32768 + (size_t)k*64);
                            float d0 = 0.f, d1 = 0.f, d2 = 0.f, d3 = 0.f;
                            #pragma unroll
                            for (int j = 0; j < 16; j++){
                                float4 e = ep[j];
                                d0 = fmaf(r[4*j+0], e.x, d0);
                                d1 = fmaf(r[4*j+1], e.y, d1);
                                d2 = fmaf(r[4*j+2], e.z, d2);
                                d3 = fmaf(r[4*j+3], e.w, d3);
                            }
                            float sex = fmaf(-2.f, (d0 + d1) + (d2 + d3),
                                             g_cbnorm[st*512 + k]);
                            if (sex < bex){ bex = sex; bk = k; }
                        }
                    }
                }
                bestk = bk;
            }
        }
        // ---- exact residual update + loss ----
        {
            const float4* ep = (const float4*)(cb + (size_t)st*32768 + (size_t)bestk*64);
            float rn = 0.f;
            #pragma unroll
            for (int j = 0; j < 16; j++){
                float4 e = ep[j];
                r[4*j+0] -= e.x; r[4*j+1] -= e.y; r[4*j+2] -= e.z; r[4*j+3] -= e.w;
                rn = fmaf(r[4*j+0], r[4*j+0], rn);
                rn = fmaf(r[4*j+1], r[4*j+1], rn);
                rn = fmaf(r[4*j+2], r[4*j+2], rn);
                rn = fmaf(r[4*j+3], r[4*j+3], rn);
            }
            rnorm2 = rn;
            lossacc += rn;
        }
    }

    // loss reduce (reuse norms area)
    lossacc = warpsum(lossacc);
    __syncthreads();
    float* red = norms_sm;
    if (l == 0) red[w] = lossacc;
    __syncthreads();
    if (tid == 0){
        float S = red[0] + red[1] + red[2] + red[3];
        atomicAdd(&g_loss, S * (1.25f / 8388608.f));
    }
    // dec_in = enc - residual
    float* dp = g_dec_in + (size_t)n * 64 * 4096 + pix;
    #pragma unroll
    for (int c = 0; c < 64; c++)
        dp[(size_t)c * 4096] = encp[(size_t)c * 4096] - r[c];
}

// ---------------- deconv1 ----------------------------------------------------
__global__ __launch_bounds__(512) void k_deconv1(const float* __restrict__ w,
                                                 const float* __restrict__ b){
    float* wsm = dynsm;   // 16384
    int tid = threadIdx.x;
    for (int i = tid; i < 16384; i += 512){
        int co = i >> 10, idx = i & 1023;
        wsm[idx*16 + co] = w[i];
    }
    __syncthreads();
    int n     = blockIdx.x >> 4;
    int chunk = blockIdx.x & 15;
    int row = tid >> 6, colA = tid & 63;
    int oh = chunk*8 + row;
    ull accA[8], accB[8];
    #pragma unroll
    for (int j = 0; j < 8; j++){ accA[j] = pack2(b[2*j], b[2*j+1]); accB[j] = accA[j]; }
    int p = oh & 1, q = colA & 1;
    int ih0 = (oh + p - 2) >> 1, ih1 = (oh + p) >> 1;
    int iwA0 = (colA + q - 2) >> 1, iwA1 = (colA + q) >> 1;
    int iwB0 = iwA0 + 32, iwB1 = iwA1 + 32;
    bool vh0 = (unsigned)ih0 < 64u, vh1 = (unsigned)ih1 < 64u;
    bool vwA0 = (unsigned)iwA0 < 64u;
    bool vwB1 = (unsigned)iwB1 < 64u;
    const float* din = g_dec_in + (size_t)n * 64 * 4096;
    const int i00 = p*4 + q, i01 = p*4 + q + 2, i10 = (p+2)*4 + q, i11 = (p+2)*4 + q + 2;
    for (int ci = 0; ci < 64; ci++){
        const float* pl = din + ci*4096;
        float vA00 = (vh0 && vwA0) ? pl[ih0*64 + iwA0] : 0.f;
        float vA01 = (vh0        ) ? pl[ih0*64 + iwA1] : 0.f;
        float vA10 = (vh1 && vwA0) ? pl[ih1*64 + iwA0] : 0.f;
        float vA11 = (vh1        ) ? pl[ih1*64 + iwA1] : 0.f;
        float vB00 = (vh0        ) ? pl[ih0*64 + iwB0] : 0.f;
        float vB01 = (vh0 && vwB1) ? pl[ih0*64 + iwB1] : 0.f;
        float vB10 = (vh1        ) ? pl[ih1*64 + iwB0] : 0.f;
        float vB11 = (vh1 && vwB1) ? pl[ih1*64 + iwB1] : 0.f;
        ull pA00 = pack2(vA00, vA00), pA01 = pack2(vA01, vA01);
        ull pA10 = pack2(vA10, vA10), pA11 = pack2(vA11, vA11);
        ull pB00 = pack2(vB00, vB00), pB01 = pack2(vB01, vB01);
        ull pB10 = pack2(vB10, vB10), pB11 = pack2(vB11, vB11);
        const ull* w00 = (const ull*)(wsm + (ci*16 + i00)*16);
        const ull* w01 = (const ull*)(wsm + (ci*16 + i01)*16);
        const ull* w10 = (const ull*)(wsm + (ci*16 + i10)*16);
        const ull* w11 = (const ull*)(wsm + (ci*16 + i11)*16);
        #pragma unroll
        for (int j = 0; j < 8; j++){
            ull a = w00[j], bb = w01[j], c = w10[j], d = w11[j];
            FMA2(accA[j], pA00, a); FMA2(accB[j], pB00, a);
            FMA2(accA[j], pA01, bb); FMA2(accB[j], pB01, bb);
            FMA2(accA[j], pA10, c); FMA2(accB[j], pB10, c);
            FMA2(accA[j], pA11, d); FMA2(accB[j], pB11, d);
        }
    }
    float* outp = g_d1 + (size_t)n * 16 * 16384 + oh*128 + colA;
    #pragma unroll
    for (int j = 0; j < 8; j++){
        float2 fA = unpack2(accA[j]), fB = unpack2(accB[j]);
        outp[(size_t)(2*j  ) * 16384]      = fA.x;
        outp[(size_t)(2*j+1) * 16384]      = fA.y;
        outp[(size_t)(2*j  ) * 16384 + 64] = fB.x;
        outp[(size_t)(2*j+1) * 16384 + 64] = fB.y;
    }
}

// ---------------- batchnorm stats --------------------------------------------
__global__ __launch_bounds__(256) void k_bnstats(){
    int c = blockIdx.x & 15, nn = blockIdx.x >> 4;
    const float4* sp = (const float4*)(g_d1 + (size_t)(nn*16 + c) * 16384);
    float s = 0.f, q = 0.f;
    for (int i = threadIdx.x; i < 4096; i += 256){
        float4 xv = sp[i];
        s += xv.x + xv.y + xv.z + xv.w;
        q = fmaf(xv.x, xv.x, fmaf(xv.y, xv.y, fmaf(xv.z, xv.z, fmaf(xv.w, xv.w, q))));
    }
    __shared__ float rsum[8], rsq[8];
    s = warpsum(s); q = warpsum(q);
    int wid = threadIdx.x >> 5, lane = threadIdx.x & 31;
    if (lane == 0){ rsum[wid] = s; rsq[wid] = q; }
    __syncthreads();
    if (threadIdx.x == 0){
        float S = 0.f, Q = 0.f;
        #pragma unroll
        for (int i = 0; i < 8; i++){ S += rsum[i]; Q += rsq[i]; }
        atomicAdd(&g_bn_s[c], S);
        atomicAdd(&g_bn_q[c], Q);
    }
}

// ---------------- deconv2 ----------------------------------------------------
__global__ __launch_bounds__(512) void k_deconv2(const float* __restrict__ w,
                                                 const float* __restrict__ b,
                                                 const float* __restrict__ gamma,
                                                 const float* __restrict__ beta,
                                                 float* __restrict__ out){
    __shared__ ull   wp[256];
    __shared__ float w2[256];
    __shared__ float Asm[16], Bsm[16];
    int tid = threadIdx.x;
    if (tid < 256){
        wp[tid] = pack2(w[tid], w[256 + tid]);
        w2[tid] = w[512 + tid];
    }
    if (tid < 16){
        const float Nc = 32.f * 128.f * 128.f;
        float m = g_bn_s[tid] / Nc;
        float var = g_bn_q[tid] / Nc - m*m;
        float A = rsqrtf(var + EPSN) * gamma[tid];
        Asm[tid] = A;
        Bsm[tid] = fmaf(-m, A, beta[tid]);
    }
    __syncthreads();
    int n     = blockIdx.x >> 6;
    int chunk = blockIdx.x & 63;
    int row = tid >> 7, colA = tid & 127;
    int oh = chunk*4 + row;
    ull accA01 = pack2(b[0], b[1]), accB01 = accA01;
    float accA2 = b[2], accB2 = b[2];
    int p = oh & 1, q = colA & 1;
    int ih0 = (oh + p - 2) >> 1, ih1 = (oh + p) >> 1;
    int iwA0 = (colA + q - 2) >> 1, iwA1 = (colA + q) >> 1;
    int iwB0 = iwA0 + 64, iwB1 = iwA1 + 64;
    bool vh0 = (unsigned)ih0 < 128u, vh1 = (unsigned)ih1 < 128u;
    bool vwA0 = (unsigned)iwA0 < 128u;
    bool vwB1 = (unsigned)iwB1 < 128u;
    const int i00 = p*4 + q, i01 = p*4 + q + 2, i10 = (p+2)*4 + q, i11 = (p+2)*4 + q + 2;
    const float* din = g_d1 + (size_t)n * 16 * 16384;
    for (int ci = 0; ci < 16; ci++){
        const float* pl = din + ci*16384;
        float A = Asm[ci], Bv = Bsm[ci];
        float vA00 = (vh0 && vwA0) ? fmaf(pl[ih0*128 + iwA0], A, Bv) : 0.f;
        float vA01 = (vh0        ) ? fmaf(pl[ih0*128 + iwA1], A, Bv) : 0.f;
        float vA10 = (vh1 && vwA0) ? fmaf(pl[ih1*128 + iwA0], A, Bv) : 0.f;
        float vA11 = (vh1        ) ? fmaf(pl[ih1*128 + iwA1], A, Bv) : 0.f;
        float vB00 = (vh0        ) ? fmaf(pl[ih0*128 + iwB0], A, Bv) : 0.f;
        float vB01 = (vh0 && vwB1) ? fmaf(pl[ih0*128 + iwB1], A, Bv) : 0.f;
        float vB10 = (vh1        ) ? fmaf(pl[ih1*128 + iwB0], A, Bv) : 0.f;
        float vB11 = (vh1 && vwB1) ? fmaf(pl[ih1*128 + iwB1], A, Bv) : 0.f;
        ull wa = wp[ci*16 + i00], wb = wp[ci*16 + i01];
        ull wc = wp[ci*16 + i10], wd = wp[ci*16 + i11];
        FMA2(accA01, pack2(vA00,vA00), wa); FMA2(accB01, pack2(vB00,vB00), wa);
        FMA2(accA01, pack2(vA01,vA01), wb); FMA2(accB01, pack2(vB01,vB01), wb);
        FMA2(accA01, pack2(vA10,vA10), wc); FMA2(accB01, pack2(vB10,vB10), wc);
        FMA2(accA01, pack2(vA11,vA11), wd); FMA2(accB01, pack2(vB11,vB11), wd);
        float s2a = w2[ci*16 + i00], s2b = w2[ci*16 + i01];
        float s2c = w2[ci*16 + i10], s2d = w2[ci*16 + i11];
        accA2 = fmaf(vA00, s2a, fmaf(vA01, s2b, fmaf(vA10, s2c, fmaf(vA11, s2d, accA2))));
        accB2 = fmaf(vB00, s2a, fmaf(vB01, s2b, fmaf(vB10, s2c, fmaf(vB11, s2d, accB2))));
    }
    float* outp = out + (size_t)n * 3 * 65536 + oh*256 + colA;
    float2 fA = unpack2(accA01), fB = unpack2(accB01);
    outp[0]            = fA.x;
    outp[65536]        = fA.y;
    outp[131072]       = accA2;
    outp[128]          = fB.x;
    outp[65536 + 128]  = fB.y;
    outp[131072 + 128] = accB2;
}

__global__ void k_write_loss(float* __restrict__ out, int idx){
    if (threadIdx.x == 0) out[idx] = g_loss;
}

// ---------------- launch -----------------------------------------------------
extern "C" void kernel_launch(void* const* d_in, const int* in_sizes, int n_in,
                              void* d_out, int out_size){
    const float* x     = (const float*)d_in[0];
    const float* ew1   = (const float*)d_in[1];
    const float* eb1   = (const float*)d_in[2];
    const float* ew2   = (const float*)d_in[3];
    const float* eb2   = (const float*)d_in[4];
    const float* cb    = (const float*)d_in[5];
    const float* dw1   = (const float*)d_in[6];
    const float* db1   = (const float*)d_in[7];
    const float* gamma = (const float*)d_in[8];
    const float* beta  = (const float*)d_in[9];
    const float* dw2   = (const float*)d_in[10];
    const float* db2   = (const float*)d_in[11];
    float* out = (float*)d_out;

    const int conv2_smem   = (16384 + 16*18*132) * 4;
    const int deconv1_smem = 16384 * 4;

    cudaFuncSetAttribute(k_conv2,    cudaFuncAttributeMaxDynamicSharedMemorySize, conv2_smem);
    cudaFuncSetAttribute(k_rvq_mma,  cudaFuncAttributeMaxDynamicSharedMemorySize, RVQ_SMEM);
    cudaFuncSetAttribute(k_deconv1,  cudaFuncAttributeMaxDynamicSharedMemorySize, deconv1_smem);

    k_zero<<<1, 32>>>();
    k_cbprep<<<6, 512>>>(cb);
    k_conv1<<<512, 512>>>(x, ew1, eb1);
    k_stats<<<512, 512>>>(0);
    k_norm<<<512, 512>>>(0);
    k_conv2<<<256, 512, conv2_smem>>>(ew2, eb2);
    k_stats<<<2048, 512>>>(1);
    k_norm<<<2048, 512>>>(1);
    k_rvq_mma<<<1024, 128, RVQ_SMEM>>>(cb);
    k_deconv1<<<512, 512, deconv1_smem>>>(dw1, db1);
    k_bnstats<<<512, 256>>>();
    k_deconv2<<<2048, 512>>>(dw2, db2, gamma, beta, out);
    k_write_loss<<<1, 32>>>(out, out_size - 1);
}

// round 6
// speedup vs baseline: 1.1214x; 1.0452x over previous
#include <cuda_runtime.h>
#include <cuda_bf16.h>
#include <cuda_fp16.h>
#include <cstdint>

#define EPSN 1e-5f

// ---------------- scratch (device globals; no allocations allowed) ----------
__device__ float g_h1[32*16*128*128];     // conv1 output (normalized in-place)
__device__ float g_enc[32*64*64*64];      // conv2 output (normalized in-place)
__device__ float g_dec_in[32*64*64*64];   // quantized (flat - residual), NCHW
__device__ float g_d1[32*16*128*128];     // deconv1 raw output
__device__ float g_m1[512],  g_v1[512];   // instance-norm stats for h1
__device__ float g_m2[2048], g_v2[2048];  // instance-norm stats for enc
__device__ float g_bn_s[16], g_bn_q[16];  // batchnorm sums
__device__ float g_loss;
__device__ __nv_bfloat16 g_cb_bf16[6*512*64];  // bf16 codebooks
__device__ float g_cbnorm[6*512];              // fp32 |e|^2 per code
__device__ float g_bmax[6];                    // max |e| per stage

extern __shared__ float dynsm[];

typedef unsigned long long ull;

#define FMA2(acc, a, b_) asm("fma.rn.f32x2 %0, %1, %2, %3;" : "=l"(acc) : "l"(a), "l"(b_), "l"(acc))

__device__ __forceinline__ float2 unpack2(ull p){
    float2 f; asm("mov.b64 {%0,%1}, %2;" : "=f"(f.x), "=f"(f.y) : "l"(p)); return f;
}
__device__ __forceinline__ ull pack2(float lo, float hi){
    ull p; asm("mov.b64 %0, {%1,%2};" : "=l"(p) : "f"(lo), "f"(hi)); return p;
}
__device__ __forceinline__ float warpsum(float v){
    #pragma unroll
    for (int o = 16; o; o >>= 1) v += __shfl_down_sync(0xffffffffu, v, o);
    return v;
}
__device__ __forceinline__ uint32_t smem_u32(const void* p){
    uint32_t a;
    asm("{ .reg .u64 t; cvta.to.shared.u64 t, %1; cvt.u32.u64 %0, t; }" : "=r"(a) : "l"(p));
    return a;
}

#define SWZ128(b) ((b) ^ (((b) >> 3) & 0x70))

// m16n8k16 bf16 mma, fp32 accumulate
__device__ __forceinline__ void mma16816(float c[4], const uint32_t a[4],
                                         uint32_t b0, uint32_t b1){
    asm volatile(
        "mma.sync.aligned.m16n8k16.row.col.f32.bf16.bf16.f32 "
        "{%0,%1,%2,%3}, {%4,%5,%6,%7}, {%8,%9}, {%0,%1,%2,%3};"
        : "+f"(c[0]), "+f"(c[1]), "+f"(c[2]), "+f"(c[3])
        : "r"(a[0]), "r"(a[1]), "r"(a[2]), "r"(a[3]), "r"(b0), "r"(b1));
}
__device__ __forceinline__ void ldsm_x4(uint32_t r[4], uint32_t addr){
    asm volatile("ldmatrix.sync.aligned.m8n8.x4.shared.b16 {%0,%1,%2,%3}, [%4];"
        : "=r"(r[0]), "=r"(r[1]), "=r"(r[2]), "=r"(r[3]) : "r"(addr));
}

// ---------------- zero accumulators ----------------------------------------
__global__ void k_zero(){
    int t = threadIdx.x;
    if (t == 0) g_loss = 0.f;
    if (t < 16){ g_bn_s[t] = 0.f; g_bn_q[t] = 0.f; }
}

// ---------------- codebook prep ----------------------------------------------
__global__ __launch_bounds__(512) void k_cbprep(const float* __restrict__ cb){
    int st = blockIdx.x, k = threadIdx.x;
    const float* row = cb + (size_t)(st*512 + k) * 64;
    float s = 0.f;
    __nv_bfloat162* dst = (__nv_bfloat162*)g_cb_bf16 + (size_t)(st*512 + k) * 32;
    #pragma unroll
    for (int j = 0; j < 32; j++){
        float a = row[2*j], b = row[2*j+1];
        s = fmaf(a, a, fmaf(b, b, s));
        dst[j] = __float22bfloat162_rn(make_float2(a, b));
    }
    g_cbnorm[st*512 + k] = s;
    __shared__ float mx[16];
    float m = s;
    #pragma unroll
    for (int o = 16; o; o >>= 1) m = fmaxf(m, __shfl_down_sync(0xffffffffu, m, o));
    int wid = k >> 5;
    if ((k & 31) == 0) mx[wid] = m;
    __syncthreads();
    if (k == 0){
        float M = 0.f;
        #pragma unroll
        for (int i = 0; i < 16; i++) M = fmaxf(M, mx[i]);
        g_bmax[st] = sqrtf(M);
    }
}

// ---------------- conv1 ------------------------------------------------------
__global__ __launch_bounds__(512) void k_conv1(const float* __restrict__ x,
                                               const float* __restrict__ w,
                                               const float* __restrict__ b){
    __shared__ float wsm[48][16];
    int tid = threadIdx.x;
    for (int i = tid; i < 768; i += 512){
        int co = i / 48, idx = i % 48;
        wsm[idx][co] = w[i];
    }
    __syncthreads();
    int n     = blockIdx.x >> 4;
    int chunk = blockIdx.x & 15;
    int row = tid >> 6, col = tid & 63;
    int oh = chunk*8 + row;
    ull accA[8], accB[8];
    #pragma unroll
    for (int j = 0; j < 8; j++){ accA[j] = pack2(b[2*j], b[2*j+1]); accB[j] = accA[j]; }
    const float* xn = x + (size_t)n * 3 * 65536;
    for (int ci = 0; ci < 3; ci++){
        #pragma unroll
        for (int kh = 0; kh < 4; kh++){
            int ih = 2*oh + kh - 1;
            if ((unsigned)ih >= 256u) continue;
            const float* rowp = xn + (ci*256 + ih)*256;
            #pragma unroll
            for (int kw = 0; kw < 4; kw++){
                int iwA = 2*col + kw - 1;
                int iwB = iwA + 128;
                float vA = ((unsigned)iwA < 256u) ? rowp[iwA] : 0.f;
                float vB = ((unsigned)iwB < 256u) ? rowp[iwB] : 0.f;
                ull vA2 = pack2(vA, vA), vB2 = pack2(vB, vB);
                const ull* wr = (const ull*)wsm[ci*16 + kh*4 + kw];
                #pragma unroll
                for (int j = 0; j < 8; j++){
                    FMA2(accA[j], vA2, wr[j]);
                    FMA2(accB[j], vB2, wr[j]);
                }
            }
        }
    }
    float* outp = g_h1 + (size_t)n * 16 * 16384 + oh*128 + col;
    #pragma unroll
    for (int j = 0; j < 8; j++){
        float2 fA = unpack2(accA[j]), fB = unpack2(accB[j]);
        outp[(size_t)(2*j  ) * 16384]      = fA.x;
        outp[(size_t)(2*j+1) * 16384]      = fA.y;
        outp[(size_t)(2*j  ) * 16384 + 64] = fB.x;
        outp[(size_t)(2*j+1) * 16384 + 64] = fB.y;
    }
}

// ---------------- per-plane mean/var ----------------------------------------
__global__ __launch_bounds__(512) void k_stats(int mode){
    int p = blockIdx.x;
    const float* sp; float* mo; float* vo; int plane;
    if (mode == 0){ sp = g_h1 + (size_t)p*16384; mo = g_m1; vo = g_v1; plane = 16384; }
    else          { sp = g_enc + (size_t)p*4096; mo = g_m2; vo = g_v2; plane = 4096; }
    float s = 0.f, q = 0.f;
    const float4* sp4 = (const float4*)sp;
    for (int i = threadIdx.x; i < plane/4; i += 512){
        float4 xv = sp4[i];
        s += xv.x + xv.y + xv.z + xv.w;
        q = fmaf(xv.x, xv.x, fmaf(xv.y, xv.y, fmaf(xv.z, xv.z, fmaf(xv.w, xv.w, q))));
    }
    __shared__ float rsum[16], rsq[16];
    s = warpsum(s); q = warpsum(q);
    int wid = threadIdx.x >> 5, lane = threadIdx.x & 31;
    if (lane == 0){ rsum[wid] = s; rsq[wid] = q; }
    __syncthreads();
    if (threadIdx.x == 0){
        float S = 0.f, Q = 0.f;
        #pragma unroll
        for (int i = 0; i < 16; i++){ S += rsum[i]; Q += rsq[i]; }
        float inv = 1.f / (float)plane;
        float mm = S * inv;
        mo[p] = mm;
        vo[p] = Q * inv - mm*mm;
    }
}

// ---------------- in-place normalize + relu ---------------------------------
__global__ __launch_bounds__(512) void k_norm(int mode){
    int p = blockIdx.x;
    float* sp; float m, r; int plane;
    if (mode == 0){ sp = g_h1 + (size_t)p*16384; m = g_m1[p]; r = rsqrtf(g_v1[p] + EPSN); plane = 16384; }
    else          { sp = g_enc + (size_t)p*4096; m = g_m2[p]; r = rsqrtf(g_v2[p] + EPSN); plane = 4096; }
    float4* sp4 = (float4*)sp;
    for (int i = threadIdx.x; i < plane/4; i += 512){
        float4 xv = sp4[i];
        xv.x = fmaxf((xv.x - m) * r, 0.f);
        xv.y = fmaxf((xv.y - m) * r, 0.f);
        xv.z = fmaxf((xv.z - m) * r, 0.f);
        xv.w = fmaxf((xv.w - m) * r, 0.f);
        sp4[i] = xv;
    }
}

// ---------------- conv2 ------------------------------------------------------
__global__ __launch_bounds__(512) void k_conv2(const float* __restrict__ w,
                                               const float* __restrict__ b){
    float* wsm = dynsm;            // 16384
    float* tile = dynsm + 16384;   // 38016 : ci*2376 + r*132 + c
    int tid = threadIdx.x;
    for (int i = tid; i < 16384; i += 512){
        int co = i >> 8, idx = i & 255;
        wsm[idx*64 + co] = w[i];
    }
    int n   = blockIdx.x >> 3;
    int oh0 = (blockIdx.x & 7) << 3;
    int ihg0 = 2*oh0 - 1;
    const float* hn = g_h1 + (size_t)n * 16 * 16384;
    for (int i = tid; i < 16*18*132; i += 512){
        int ci = i / 2376, rem = i % 2376;
        int r = rem / 132, c = rem % 132;
        int ihg = ihg0 + r, iwg = c - 1;
        float v = 0.f;
        if ((unsigned)ihg < 128u && (unsigned)iwg < 128u)
            v = hn[(ci*128 + ihg)*128 + iwg];
        tile[i] = v;
    }
    __syncthreads();
    int ohl = tid >> 6, ow = tid & 63;
    ull acc[32];
    #pragma unroll
    for (int j = 0; j < 32; j++) acc[j] = pack2(b[2*j], b[2*j+1]);
    for (int ci = 0; ci < 16; ci++){
        const float* tci = tile + ci*2376;
        #pragma unroll
        for (int kh = 0; kh < 4; kh++){
            const float* trow = tci + (2*ohl + kh)*132 + 2*ow;
            #pragma unroll
            for (int kw = 0; kw < 4; kw++){
                float v = trow[kw];
                ull v2 = pack2(v, v);
                const ull* wr = (const ull*)(wsm + (ci*16 + kh*4 + kw)*64);
                #pragma unroll
                for (int j = 0; j < 32; j++) FMA2(acc[j], v2, wr[j]);
            }
        }
    }
    int oh = oh0 + ohl;
    float* outp = g_enc + (size_t)n * 64 * 4096 + oh*64 + ow;
    #pragma unroll
    for (int j = 0; j < 32; j++){
        float2 f = unpack2(acc[j]);
        outp[(size_t)(2*j  ) * 4096] = f.x;
        outp[(size_t)(2*j+1) * 4096] = f.y;
    }
}

// ---------------- RVQ via warp MMA (HMMA bf16) -------------------------------
// scores stride 1036 B (259 words, odd) -> conflict-free 4B row scans
#define CB_OFF   0
#define A_OFF    65536
#define NORM_OFF 81920
#define SC_OFF   83968
#define SC_STRIDE 1036
#define RVQ_SMEM (83968 + 128*SC_STRIDE)

__global__ __launch_bounds__(128) void k_rvq_mma(const float* __restrict__ cb){
    char* smc = (char*)dynsm;
    float* norms_sm = (float*)(smc + NORM_OFF);
    uint32_t sb = smem_u32(smc);
    int tid = threadIdx.x;
    int w = tid >> 5, l = tid & 31;
    int g = l >> 2, tig = l & 3;

    int n   = blockIdx.x >> 5;
    int pix = ((blockIdx.x & 31) << 7) + tid;
    const float* encp = g_enc + (size_t)n * 64 * 4096 + pix;

    float r[64];
    float rnorm2 = 0.f;
    #pragma unroll
    for (int c = 0; c < 64; c++){
        r[c] = encp[(size_t)c * 4096];
        rnorm2 = fmaf(r[c], r[c], rnorm2);
    }
    float lossacc = 0.f;

    for (int st = 0; st < 6; st++){
        {
            const uint4* csrc = (const uint4*)(g_cb_bf16 + (size_t)st * 32768);
            for (int i = tid; i < 4096; i += 128){
                int code = i >> 3, cc = i & 7;
                uint32_t byte = (uint32_t)code*128 + cc*16;
                *(uint4*)(smc + CB_OFF + (byte ^ ((code & 7) << 4))) = csrc[i];
            }
            #pragma unroll
            for (int i = tid; i < 512; i += 128)
                norms_sm[i] = g_cbnorm[st*512 + i];
        }
        #pragma unroll
        for (int j = 0; j < 32; j++){
            __nv_bfloat162 v = __float22bfloat162_rn(make_float2(r[2*j], r[2*j+1]));
            uint32_t byte = (uint32_t)tid*128 + j*4;
            *(uint32_t*)(smc + A_OFF + SWZ128(byte)) = *(uint32_t*)&v;
        }
        __syncthreads();

        {
            int arow_lo = (l & 7) + ((l >> 3) & 1) * 8;
            int akb     = ((l >> 4) & 1) * 16;
            int t4 = l >> 3;
            int brow_lo = ((t4 >> 1) & 1) * 8 + (l & 7);
            int bkb     = (t4 & 1) * 16;

            for (int m = 0; m < 8; m++){
                uint32_t afr[4][4];
                #pragma unroll
                for (int k = 0; k < 4; k++){
                    uint32_t byte = (uint32_t)(m*16 + arow_lo)*128 + (k*32 + akb);
                    ldsm_x4(afr[k], sb + A_OFF + SWZ128(byte));
                }
                for (int ch = 0; ch < 8; ch++){
                    int nbase = w*128 + ch*16;
                    uint32_t bfr[4][4];
                    #pragma unroll
                    for (int k = 0; k < 4; k++){
                        uint32_t byte = (uint32_t)(nbase + brow_lo)*128 + (k*32 + bkb);
                        ldsm_x4(bfr[k], sb + CB_OFF + SWZ128(byte));
                    }
                    float clo[4] = {0.f,0.f,0.f,0.f};
                    float chi[4] = {0.f,0.f,0.f,0.f};
                    #pragma unroll
                    for (int k = 0; k < 4; k++){
                        mma16816(clo, afr[k], bfr[k][0], bfr[k][1]);
                        mma16816(chi, afr[k], bfr[k][2], bfr[k][3]);
                    }
                    int col0 = nbase + tig*2;
                    int col1 = col0 + 8;
                    float2 nm0 = *(float2*)(norms_sm + col0);
                    float2 nm1 = *(float2*)(norms_sm + col1);
                    int row0 = m*16 + g;
                    char* p0 = smc + SC_OFF + (size_t)row0*SC_STRIDE;
                    char* p1 = p0 + 8*SC_STRIDE;
                    float s00 = fmaf(-2.f, clo[0], nm0.x);
                    float s01 = fmaf(-2.f, clo[1], nm0.y);
                    float s10 = fmaf(-2.f, clo[2], nm0.x);
                    float s11 = fmaf(-2.f, clo[3], nm0.y);
                    float t00 = fmaf(-2.f, chi[0], nm1.x);
                    float t01 = fmaf(-2.f, chi[1], nm1.y);
                    float t10 = fmaf(-2.f, chi[2], nm1.x);
                    float t11 = fmaf(-2.f, chi[3], nm1.y);
                    *(__half2*)(p0 + col0*2) = __floats2half2_rn(s00, s01);
                    *(__half2*)(p1 + col0*2) = __floats2half2_rn(s10, s11);
                    *(__half2*)(p0 + col1*2) = __floats2half2_rn(t00, t01);
                    *(__half2*)(p1 + col1*2) = __floats2half2_rn(t10, t11);
                }
            }
        }
        __syncthreads();

        const char* srowb = smc + SC_OFF + (size_t)tid*SC_STRIDE;
        float mn1 = 3.4e38f, mn2 = 3.4e38f; int idx = 0;
        #pragma unroll 4
        for (int i = 0; i < 256; i++){
            float2 s = __half22float2(*(const __half2*)(srowb + i*4));
            if (s.x < mn1){ mn2 = mn1; mn1 = s.x; idx = 2*i; }
            else if (s.x < mn2) mn2 = s.x;
            if (s.y < mn1){ mn2 = mn1; mn1 = s.y; idx = 2*i+1; }
            else if (s.y < mn2) mn2 = s.y;
        }
        float srn  = sqrtf(rnorm2);
        float bmax = g_bmax[st];
        float margin = fmaf(0.0157f*srn, bmax,
                       fmaf(5e-4f, fmaf(2.f*srn, bmax, bmax*bmax), 1e-3f));
        int bestk = idx;
        bool need = (mn2 - mn1) <= 2.f * margin;
        if (__any_sync(0xffffffffu, need)){
            float thresh = mn1 + 2.f * margin;
            if (need){
                float bex = 3.4e38f; int bk = idx;
                for (int i = 0; i < 256; i++){
                    float2 s = __half22float2(*(const __half2*)(srowb + i*4));
                    #pragma unroll
                    for (int half = 0; half < 2; half++){
                        float sv = half ? s.y : s.x;
                        if (sv <= thresh){
                            int k = 2*i + half;
                            const float4* ep = (const float4*)(cb + (size_t)st*32768 + (size_t)k*64);
                            float d0 = 0.f, d1 = 0.f, d2 = 0.f, d3 = 0.f;
                            #pragma unroll
                            for (int j = 0; j < 16; j++){
                                float4 e = ep[j];
                                d0 = fmaf(r[4*j+0], e.x, d0);
                                d1 = fmaf(r[4*j+1], e.y, d1);
                                d2 = fmaf(r[4*j+2], e.z, d2);
                                d3 = fmaf(r[4*j+3], e.w, d3);
                            }
                            float sex = fmaf(-2.f, (d0 + d1) + (d2 + d3),
                                             g_cbnorm[st*512 + k]);
                            if (sex < bex){ bex = sex; bk = k; }
                        }
                    }
                }
                bestk = bk;
            }
        }
        {
            const float4* ep = (const float4*)(cb + (size_t)st*32768 + (size_t)bestk*64);
            float rn = 0.f;
            #pragma unroll
            for (int j = 0; j < 16; j++){
                float4 e = ep[j];
                r[4*j+0] -= e.x; r[4*j+1] -= e.y; r[4*j+2] -= e.z; r[4*j+3] -= e.w;
                rn = fmaf(r[4*j+0], r[4*j+0], rn);
                rn = fmaf(r[4*j+1], r[4*j+1], rn);
                rn = fmaf(r[4*j+2], r[4*j+2], rn);
                rn = fmaf(r[4*j+3], r[4*j+3], rn);
            }
            rnorm2 = rn;
            lossacc += rn;
        }
    }

    lossacc = warpsum(lossacc);
    __syncthreads();
    float* red = norms_sm;
    if (l == 0) red[w] = lossacc;
    __syncthreads();
    if (tid == 0){
        float S = red[0] + red[1] + red[2] + red[3];
        atomicAdd(&g_loss, S * (1.25f / 8388608.f));
    }
    float* dp = g_dec_in + (size_t)n * 64 * 4096 + pix;
    #pragma unroll
    for (int c = 0; c < 64; c++)
        dp[(size_t)c * 4096] = encp[(size_t)c * 4096] - r[c];
}

// ---------------- deconv1 (smem-tiled): g_dec_in -> g_d1 ---------------------
// block = 8 out rows x 128 cols, 512 thr x 2px (col, col+64); grid 32n x 16.
// smem: wsm 16384 f + tile 64ci x 6 x 68 = 26112 f  => 169984 B
__global__ __launch_bounds__(512) void k_deconv1(const float* __restrict__ w,
                                                 const float* __restrict__ b){
    float* wsm  = dynsm;            // (ci*16+kh*4+kw)*16 + co
    float* tile = dynsm + 16384;    // ci*408 + r*68 + c
    int tid = threadIdx.x;
    for (int i = tid; i < 16384; i += 512){
        int co = i >> 10, idx = i & 1023;
        wsm[idx*16 + co] = w[i];
    }
    int n     = blockIdx.x >> 4;
    int chunk = blockIdx.x & 15;
    int ihg0 = chunk*4 - 1;
    const float* din = g_dec_in + (size_t)n * 64 * 4096;
    for (int i = tid; i < 64*6*68; i += 512){
        int ci = i / 408, rem = i % 408;
        int rr = rem / 68, c = rem % 68;
        int ihg = ihg0 + rr, iwg = c - 1;
        float v = 0.f;
        if ((unsigned)ihg < 64u && (unsigned)iwg < 64u)
            v = din[ci*4096 + ihg*64 + iwg];
        tile[i] = v;
    }
    __syncthreads();

    int rowl = tid >> 6, colA = tid & 63;
    int oh = chunk*8 + rowl;
    ull accA[8], accB[8];
    #pragma unroll
    for (int j = 0; j < 8; j++){ accA[j] = pack2(b[2*j], b[2*j+1]); accB[j] = accA[j]; }
    int p = rowl & 1, q = colA & 1;
    int lih0 = ((rowl + p - 2) >> 1) + 1;      // in [0,4]
    int lih1 = lih0 + 1;
    int liwA0 = ((colA + q - 2) >> 1) + 1;     // in [0,32]
    int liwA1 = liwA0 + 1;
    const int i00 = p*4 + q, i01 = p*4 + q + 2, i10 = (p+2)*4 + q, i11 = (p+2)*4 + q + 2;
    for (int ci = 0; ci < 64; ci++){
        const float* tb = tile + ci*408;
        const float* r0 = tb + lih0*68;
        const float* r1 = tb + lih1*68;
        float vA00 = r0[liwA0], vA01 = r0[liwA1];
        float vA10 = r1[liwA0], vA11 = r1[liwA1];
        float vB00 = r0[liwA0+32], vB01 = r0[liwA1+32];
        float vB10 = r1[liwA0+32], vB11 = r1[liwA1+32];
        ull pA00 = pack2(vA00, vA00), pA01 = pack2(vA01, vA01);
        ull pA10 = pack2(vA10, vA10), pA11 = pack2(vA11, vA11);
        ull pB00 = pack2(vB00, vB00), pB01 = pack2(vB01, vB01);
        ull pB10 = pack2(vB10, vB10), pB11 = pack2(vB11, vB11);
        const ull* w00 = (const ull*)(wsm + (ci*16 + i00)*16);
        const ull* w01 = (const ull*)(wsm + (ci*16 + i01)*16);
        const ull* w10 = (const ull*)(wsm + (ci*16 + i10)*16);
        const ull* w11 = (const ull*)(wsm + (ci*16 + i11)*16);
        #pragma unroll
        for (int j = 0; j < 8; j++){
            ull a = w00[j], bb = w01[j], c = w10[j], d = w11[j];
            FMA2(accA[j], pA00, a); FMA2(accB[j], pB00, a);
            FMA2(accA[j], pA01, bb); FMA2(accB[j], pB01, bb);
            FMA2(accA[j], pA10, c); FMA2(accB[j], pB10, c);
            FMA2(accA[j], pA11, d); FMA2(accB[j], pB11, d);
        }
    }
    float* outp = g_d1 + (size_t)n * 16 * 16384 + oh*128 + colA;
    #pragma unroll
    for (int j = 0; j < 8; j++){
        float2 fA = unpack2(accA[j]), fB = unpack2(accB[j]);
        outp[(size_t)(2*j  ) * 16384]      = fA.x;
        outp[(size_t)(2*j+1) * 16384]      = fA.y;
        outp[(size_t)(2*j  ) * 16384 + 64] = fB.x;
        outp[(size_t)(2*j+1) * 16384 + 64] = fB.y;
    }
}

// ---------------- batchnorm stats --------------------------------------------
__global__ __launch_bounds__(256) void k_bnstats(){
    int c = blockIdx.x & 15, nn = blockIdx.x >> 4;
    const float4* sp = (const float4*)(g_d1 + (size_t)(nn*16 + c) * 16384);
    float s = 0.f, q = 0.f;
    for (int i = threadIdx.x; i < 4096; i += 256){
        float4 xv = sp[i];
        s += xv.x + xv.y + xv.z + xv.w;
        q = fmaf(xv.x, xv.x, fmaf(xv.y, xv.y, fmaf(xv.z, xv.z, fmaf(xv.w, xv.w, q))));
    }
    __shared__ float rsum[8], rsq[8];
    s = warpsum(s); q = warpsum(q);
    int wid = threadIdx.x >> 5, lane = threadIdx.x & 31;
    if (lane == 0){ rsum[wid] = s; rsq[wid] = q; }
    __syncthreads();
    if (threadIdx.x == 0){
        float S = 0.f, Q = 0.f;
        #pragma unroll
        for (int i = 0; i < 8; i++){ S += rsum[i]; Q += rsq[i]; }
        atomicAdd(&g_bn_s[c], S);
        atomicAdd(&g_bn_q[c], Q);
    }
}

// ---------------- deconv2 (smem-tiled): BN(g_d1) -> decoded ------------------
// block = 8 out rows x 256 cols, 512 thr x 4px (col, +64, +128, +192);
// grid 32n x 32. smem: tile 16ci x 6 x 132 = 12672 f (BN pre-applied).
__global__ __launch_bounds__(512) void k_deconv2(const float* __restrict__ w,
                                                 const float* __restrict__ b,
                                                 const float* __restrict__ gamma,
                                                 const float* __restrict__ beta,
                                                 float* __restrict__ out){
    __shared__ ull   wp[256];
    __shared__ float w2[256];
    __shared__ float Asm[16], Bsm[16];
    float* tile = dynsm;   // ci*792 + r*132 + c
    int tid = threadIdx.x;
    if (tid < 256){
        wp[tid] = pack2(w[tid], w[256 + tid]);
        w2[tid] = w[512 + tid];
    }
    if (tid < 16){
        const float Nc = 32.f * 128.f * 128.f;
        float m = g_bn_s[tid] / Nc;
        float var = g_bn_q[tid] / Nc - m*m;
        float A = rsqrtf(var + EPSN) * gamma[tid];
        Asm[tid] = A;
        Bsm[tid] = fmaf(-m, A, beta[tid]);
    }
    __syncthreads();

    int n     = blockIdx.x >> 5;
    int chunk = blockIdx.x & 31;
    int ihg0 = chunk*4 - 1;
    const float* din = g_d1 + (size_t)n * 16 * 16384;
    for (int i = tid; i < 16*6*132; i += 512){
        int ci = i / 792, rem = i % 792;
        int rr = rem / 132, c = rem % 132;
        int ihg = ihg0 + rr, iwg = c - 1;
        float v = 0.f;
        if ((unsigned)ihg < 128u && (unsigned)iwg < 128u)
            v = fmaf(din[ci*16384 + ihg*128 + iwg], Asm[ci], Bsm[ci]);
        tile[i] = v;
    }
    __syncthreads();

    int rowl = tid >> 6, colA = tid & 63;
    int oh = chunk*8 + rowl;
    ull acc01[4];
    float acc2[4];
    #pragma unroll
    for (int px = 0; px < 4; px++){ acc01[px] = pack2(b[0], b[1]); acc2[px] = b[2]; }
    int p = rowl & 1, q = colA & 1;
    int lih0 = ((rowl + p - 2) >> 1) + 1;
    int lih1 = lih0 + 1;
    int liw0 = ((colA + q - 2) >> 1) + 1;   // px adds +32 each
    const int i00 = p*4 + q, i01 = p*4 + q + 2, i10 = (p+2)*4 + q, i11 = (p+2)*4 + q + 2;
    for (int ci = 0; ci < 16; ci++){
        const float* tb = tile + ci*792;
        const float* r0 = tb + lih0*132;
        const float* r1 = tb + lih1*132;
        ull wa = wp[ci*16 + i00], wb = wp[ci*16 + i01];
        ull wc = wp[ci*16 + i10], wd = wp[ci*16 + i11];
        float s2a = w2[ci*16 + i00], s2b = w2[ci*16 + i01];
        float s2c = w2[ci*16 + i10], s2d = w2[ci*16 + i11];
        #pragma unroll
        for (int px = 0; px < 4; px++){
            int o = liw0 + px*32;
            float v00 = r0[o], v01 = r0[o+1];
            float v10 = r1[o], v11 = r1[o+1];
            FMA2(acc01[px], pack2(v00,v00), wa);
            FMA2(acc01[px], pack2(v01,v01), wb);
            FMA2(acc01[px], pack2(v10,v10), wc);
            FMA2(acc01[px], pack2(v11,v11), wd);
            acc2[px] = fmaf(v00, s2a, fmaf(v01, s2b, fmaf(v10, s2c, fmaf(v11, s2d, acc2[px]))));
        }
    }
    float* outp = out + (size_t)n * 3 * 65536 + oh*256 + colA;
    #pragma unroll
    for (int px = 0; px < 4; px++){
        float2 f01 = unpack2(acc01[px]);
        outp[px*64]          = f01.x;
        outp[px*64 + 65536]  = f01.y;
        outp[px*64 + 131072] = acc2[px];
    }
}

__global__ void k_write_loss(float* __restrict__ out, int idx){
    if (threadIdx.x == 0) out[idx] = g_loss;
}

// ---------------- launch -----------------------------------------------------
extern "C" void kernel_launch(void* const* d_in, const int* in_sizes, int n_in,
                              void* d_out, int out_size){
    const float* x     = (const float*)d_in[0];
    const float* ew1   = (const float*)d_in[1];
    const float* eb1   = (const float*)d_in[2];
    const float* ew2   = (const float*)d_in[3];
    const float* eb2   = (const float*)d_in[4];
    const float* cb    = (const float*)d_in[5];
    const float* dw1   = (const float*)d_in[6];
    const float* db1   = (const float*)d_in[7];
    const float* gamma = (const float*)d_in[8];
    const float* beta  = (const float*)d_in[9];
    const float* dw2   = (const float*)d_in[10];
    const float* db2   = (const float*)d_in[11];
    float* out = (float*)d_out;

    const int conv2_smem   = (16384 + 16*18*132) * 4;
    const int deconv1_smem = (16384 + 64*6*68) * 4;    // 169984 B
    const int deconv2_smem = (16*6*132) * 4;           // 50688 B

    cudaFuncSetAttribute(k_conv2,    cudaFuncAttributeMaxDynamicSharedMemorySize, conv2_smem);
    cudaFuncSetAttribute(k_rvq_mma,  cudaFuncAttributeMaxDynamicSharedMemorySize, RVQ_SMEM);
    cudaFuncSetAttribute(k_deconv1,  cudaFuncAttributeMaxDynamicSharedMemorySize, deconv1_smem);
    cudaFuncSetAttribute(k_deconv2,  cudaFuncAttributeMaxDynamicSharedMemorySize, deconv2_smem);

    k_zero<<<1, 32>>>();
    k_cbprep<<<6, 512>>>(cb);
    k_conv1<<<512, 512>>>(x, ew1, eb1);
    k_stats<<<512, 512>>>(0);
    k_norm<<<512, 512>>>(0);
    k_conv2<<<256, 512, conv2_smem>>>(ew2, eb2);
    k_stats<<<2048, 512>>>(1);
    k_norm<<<2048, 512>>>(1);
    k_rvq_mma<<<1024, 128, RVQ_SMEM>>>(cb);
    k_deconv1<<<512, 512, deconv1_smem>>>(dw1, db1);
    k_bnstats<<<512, 256>>>();
    k_deconv2<<<1024, 512, deconv2_smem>>>(dw2, db2, gamma, beta, out);
    k_write_loss<<<1, 32>>>(out, out_size - 1);
}